// round 6
// baseline (speedup 1.0000x reference)
#include <cuda_runtime.h>

#define NPTS 80000
#define NSAMP 16
#define PAIRS (NPTS*NSAMP)
#define EPSF 1e-5f
#define INV_N (1.0f/80000.0f)
#define INV_P (1.0f/1280000.0f)
#define GEMM_BLOCKS 1250
#define PST_BLOCKS  1024
#define WS_BLOCKS   888

// ---------------- scratch (device-global) ----------------
#define OFF_T1    0
#define OFF_Q     5120000
#define OFF_K     10240000
#define OFF_V     15360000
#define OFF_W1B   20480000
#define OFF_AGG   30720000
#define OFF_T3    35840000
#define OFF_U     40960000           /* float4 per pair: u0,u1,u2,pad */
#define OFF_STATS 46080000
__device__ float g_scr[46080640];

// stats sublayout:
//  +0   bn1 sum(64)   | +64  bn1 sq(64)
//  +128 bnp sum(3)    | +136 bnp sq(3)
//  +144 bnw1 sum(64)  | +208 bnw1 sq(64)
//  +272 bnw2 sum(8)   | +280 bnw2 sq(8)
//  +288 bn2 sum(64)   | +352 bn2 sq(64)
//  +416 bn3 sum(64)   | +480 bn3 sq(64)

__global__ void k_zero(float* st) { int i = threadIdx.x; if (i < 544) st[i] = 0.f; }

// ---------------------------------------------------------------------------
// heterogeneous: blocks [0,1250) = gemm1 (t1 = x@W1, fused bn1 stats);
//                blocks [1250,2274) = pstats (+ u store)
__global__ void __launch_bounds__(256) k_g1p(
        const float* __restrict__ X, const float* __restrict__ W,
        float* __restrict__ out, float* __restrict__ st,
        const float* __restrict__ p, const int* __restrict__ knn,
        const float* __restrict__ Wp1, const float* __restrict__ bp1,
        float4* __restrict__ U)
{
    const int tid = threadIdx.x;
    if (blockIdx.x < GEMM_BLOCKS) {
        __shared__ float sX[64][65];
        __shared__ float sW[64][64];
        __shared__ float sS[64], sQ[64];
        const long row0 = (long)blockIdx.x * 64;
        if (tid < 64) { sS[tid] = 0.f; sQ[tid] = 0.f; }
        for (int i = tid; i < 4096; i += 256) sW[i >> 6][i & 63] = W[i];
        for (int i = tid; i < 4096; i += 256) {
            int r = i >> 6, kk = i & 63;
            sX[r][kk] = X[(row0 + r) * 64 + kk];
        }
        __syncthreads();
        const int lane = tid & 31;
        const int r = tid & 63, c0 = (tid >> 6) << 4;
        float acc[16];
#pragma unroll
        for (int j = 0; j < 16; j++) acc[j] = 0.f;
#pragma unroll
        for (int kk = 0; kk < 64; kk++) {
            float xv = sX[r][kk];
#pragma unroll
            for (int j = 0; j < 16; j++) acc[j] = fmaf(xv, sW[kk][c0 + j], acc[j]);
        }
        float* op = out + (row0 + r) * 64 + c0;
#pragma unroll
        for (int j = 0; j < 16; j++) op[j] = acc[j];
#pragma unroll
        for (int j = 0; j < 16; j++) {
            float s = acc[j], q = acc[j] * acc[j];
#pragma unroll
            for (int off = 16; off; off >>= 1) {
                s += __shfl_xor_sync(0xffffffffu, s, off);
                q += __shfl_xor_sync(0xffffffffu, q, off);
            }
            if (lane == 0) { atomicAdd(&sS[c0 + j], s); atomicAdd(&sQ[c0 + j], q); }
        }
        __syncthreads();
        if (tid < 64) {
            atomicAdd(&st[tid], sS[tid]);
            atomicAdd(&st[64 + tid], sQ[tid]);
        }
    } else {
        float w[9], bb[3];
#pragma unroll
        for (int i = 0; i < 9; i++) w[i] = __ldg(&Wp1[i]);
#pragma unroll
        for (int j = 0; j < 3; j++) bb[j] = __ldg(&bp1[j]);
        float s0=0,s1=0,s2=0,q0=0,q1=0,q2=0;
        const int bid = blockIdx.x - GEMM_BLOCKS;
        const int stride = PST_BLOCKS * 256;
        for (int pr = bid * 256 + tid; pr < PAIRS; pr += stride) {
            int n = pr >> 4;
            int idx = __ldg(&knn[pr]);
            float ax = p[idx*3+0]-p[n*3+0];
            float ay = p[idx*3+1]-p[n*3+1];
            float az = p[idx*3+2]-p[n*3+2];
            float u0 = fmaf(ax,w[0],fmaf(ay,w[3],fmaf(az,w[6],bb[0])));
            float u1 = fmaf(ax,w[1],fmaf(ay,w[4],fmaf(az,w[7],bb[1])));
            float u2 = fmaf(ax,w[2],fmaf(ay,w[5],fmaf(az,w[8],bb[2])));
            U[pr] = make_float4(u0, u1, u2, 0.f);
            s0+=u0; s1+=u1; s2+=u2;
            q0=fmaf(u0,u0,q0); q1=fmaf(u1,u1,q1); q2=fmaf(u2,u2,q2);
        }
#pragma unroll
        for (int off = 16; off; off >>= 1) {
            s0 += __shfl_xor_sync(0xffffffffu, s0, off);
            s1 += __shfl_xor_sync(0xffffffffu, s1, off);
            s2 += __shfl_xor_sync(0xffffffffu, s2, off);
            q0 += __shfl_xor_sync(0xffffffffu, q0, off);
            q1 += __shfl_xor_sync(0xffffffffu, q1, off);
            q2 += __shfl_xor_sync(0xffffffffu, q2, off);
        }
        __shared__ float sm[6];
        if (tid < 6) sm[tid] = 0.f;
        __syncthreads();
        if ((tid & 31) == 0) {
            atomicAdd(&sm[0], s0); atomicAdd(&sm[1], s1); atomicAdd(&sm[2], s2);
            atomicAdd(&sm[3], q0); atomicAdd(&sm[4], q1); atomicAdd(&sm[5], q2);
        }
        __syncthreads();
        if (tid < 3) {
            atomicAdd(&st[128 + tid], sm[tid]);
            atomicAdd(&st[136 + tid], sm[3 + tid]);
        }
    }
}

// q,k fused (t1 tile + bn1 loaded once, both weight matrices looped)
__global__ void __launch_bounds__(256) k_qk(
        const float* __restrict__ T1,
        const float* __restrict__ Wq, const float* __restrict__ bq,
        const float* __restrict__ Wk, const float* __restrict__ bk,
        const float* __restrict__ st,
        const float* __restrict__ g1, const float* __restrict__ b1,
        float* __restrict__ oq, float* __restrict__ ok)
{
    __shared__ float sX[64][65];
    __shared__ float sW[64][64];
    __shared__ float sA[64], sC[64];
    const int tid = threadIdx.x;
    const long row0 = (long)blockIdx.x * 64;
    if (tid < 64) {
        float m = st[tid] * INV_N;
        float var = fmaf(-m, m, st[64 + tid] * INV_N);
        float a = g1[tid] * rsqrtf(var + EPSF);
        sA[tid] = a; sC[tid] = fmaf(-m, a, b1[tid]);
    }
    __syncthreads();
    for (int i = tid; i < 4096; i += 256) {
        int r = i >> 6, kk = i & 63;
        sX[r][kk] = fmaxf(fmaf(T1[(row0 + r) * 64 + kk], sA[kk], sC[kk]), 0.f);
    }
    const int r = tid & 63, c0 = (tid >> 6) << 4;
    const float* Ws[2] = {Wq, Wk};
    const float* Bs[2] = {bq, bk};
    float* Os[2] = {oq, ok};
#pragma unroll 1
    for (int m = 0; m < 2; m++) {
        __syncthreads();
        for (int i = tid; i < 4096; i += 256) sW[i >> 6][i & 63] = Ws[m][i];
        __syncthreads();
        float acc[16];
#pragma unroll
        for (int j = 0; j < 16; j++) acc[j] = __ldg(&Bs[m][c0 + j]);
#pragma unroll
        for (int kk = 0; kk < 64; kk++) {
            float xv = sX[r][kk];
#pragma unroll
            for (int j = 0; j < 16; j++) acc[j] = fmaf(xv, sW[kk][c0 + j], acc[j]);
        }
        float* op = Os[m] + (row0 + r) * 64 + c0;
#pragma unroll
        for (int j = 0; j < 16; j++) op[j] = acc[j];
    }
}

// ---------------------------------------------------------------------------
__device__ __forceinline__ void bnp_params(const float* st, const float* bnpg,
                                           const float* bnpb,
                                           float& A0, float& A1, float& A2,
                                           float& C0, float& C1, float& C2)
{
    float m0 = __ldg(&st[128]) * INV_P;
    A0 = __ldg(&bnpg[0]) * rsqrtf(fmaf(-m0, m0, __ldg(&st[136]) * INV_P) + EPSF);
    C0 = fmaf(-m0, A0, __ldg(&bnpb[0]));
    float m1 = __ldg(&st[129]) * INV_P;
    A1 = __ldg(&bnpg[1]) * rsqrtf(fmaf(-m1, m1, __ldg(&st[137]) * INV_P) + EPSF);
    C1 = fmaf(-m1, A1, __ldg(&bnpb[1]));
    float m2 = __ldg(&st[130]) * INV_P;
    A2 = __ldg(&bnpg[2]) * rsqrtf(fmaf(-m2, m2, __ldg(&st[138]) * INV_P) + EPSF);
    C2 = fmaf(-m2, A2, __ldg(&bnpb[2]));
}

// stage (idx*64, relu(bn(u))) for 16 neighbors of point n into smem (lanes 0..15)
__device__ __forceinline__ void stage_nb(float4* row, int n, int lane,
                                         const int* __restrict__ knn,
                                         const float4* __restrict__ U,
                                         float A0, float A1, float A2,
                                         float C0, float C1, float C2)
{
    if (lane < 16) {
        int mk = __ldg(&knn[n*16 + lane]) << 6;   // element offset into 64-ch rows
        float4 uu = __ldg(&U[n*16 + lane]);
        float t0 = fmaxf(fmaf(uu.x, A0, C0), 0.f);
        float t1 = fmaxf(fmaf(uu.y, A1, C1), 0.f);
        float t2 = fmaxf(fmaf(uu.z, A2, C2), 0.f);
        row[lane] = make_float4(__int_as_float(mk), t0, t1, t2);
    }
    __syncwarp();
}

// ---------------------------------------------------------------------------
// heterogeneous: blocks [0,1250) = v GEMM (bn1 inline);
//                blocks [1250,2138) = wstats (stats of w = k_g - q + pe)
__global__ void __launch_bounds__(256) k_vws(
        const float* __restrict__ T1,
        const float* __restrict__ Wv, const float* __restrict__ bv,
        const float* __restrict__ g1, const float* __restrict__ b1,
        float* __restrict__ ov,
        const int* __restrict__ knn,
        const float* __restrict__ Qm, const float* __restrict__ Km,
        const float4* __restrict__ U,
        const float* __restrict__ bnpg, const float* __restrict__ bnpb,
        const float* __restrict__ Wp2, const float* __restrict__ bp2,
        float* __restrict__ st)
{
    const int tid = threadIdx.x;
    if (blockIdx.x < GEMM_BLOCKS) {
        __shared__ float sX[64][65];
        __shared__ float sW[64][64];
        __shared__ float sA[64], sC[64];
        const long row0 = (long)blockIdx.x * 64;
        if (tid < 64) {
            float m = st[tid] * INV_N;
            float var = fmaf(-m, m, st[64 + tid] * INV_N);
            float a = g1[tid] * rsqrtf(var + EPSF);
            sA[tid] = a; sC[tid] = fmaf(-m, a, b1[tid]);
        }
        for (int i = tid; i < 4096; i += 256) sW[i >> 6][i & 63] = Wv[i];
        __syncthreads();
        for (int i = tid; i < 4096; i += 256) {
            int r = i >> 6, kk = i & 63;
            sX[r][kk] = fmaxf(fmaf(T1[(row0 + r) * 64 + kk], sA[kk], sC[kk]), 0.f);
        }
        __syncthreads();
        const int r = tid & 63, c0 = (tid >> 6) << 4;
        float acc[16];
#pragma unroll
        for (int j = 0; j < 16; j++) acc[j] = __ldg(&bv[c0 + j]);
#pragma unroll
        for (int kk = 0; kk < 64; kk++) {
            float xv = sX[r][kk];
#pragma unroll
            for (int j = 0; j < 16; j++) acc[j] = fmaf(xv, sW[kk][c0 + j], acc[j]);
        }
        float* op = ov + (row0 + r) * 64 + c0;
#pragma unroll
        for (int j = 0; j < 16; j++) op[j] = acc[j];
    } else {
        __shared__ float4 sNb[8][16];
        __shared__ float sS[64], sQ[64];
        const int lane = tid & 31, wl = tid >> 5;
        const int ch0 = lane * 2, ch1 = ch0 + 1;
        float A0,A1,A2,C0,C1,C2; bnp_params(st, bnpg, bnpb, A0,A1,A2,C0,C1,C2);
        float P00=__ldg(&Wp2[ch0]), P10=__ldg(&Wp2[64+ch0]), P20=__ldg(&Wp2[128+ch0]), B0=__ldg(&bp2[ch0]);
        float P01=__ldg(&Wp2[ch1]), P11=__ldg(&Wp2[64+ch1]), P21=__ldg(&Wp2[128+ch1]), B1=__ldg(&bp2[ch1]);
        float s0=0,q0=0,s1=0,q1=0;
        const int warp = ((blockIdx.x - GEMM_BLOCKS) * 256 + tid) >> 5;
        const int nw = (WS_BLOCKS * 256) >> 5;
        for (int n = warp; n < NPTS; n += nw) {
            float2 qv = ((const float2*)(Qm + (long)n*64))[lane];
            float qb0 = B0 - qv.x, qb1 = B1 - qv.y;
            stage_nb(sNb[wl], n, lane, knn, U, A0,A1,A2, C0,C1,C2);
#pragma unroll
            for (int nb = 0; nb < 4; nb++) {
                float4 d0 = sNb[wl][nb*4+0];
                float4 d1 = sNb[wl][nb*4+1];
                float4 d2 = sNb[wl][nb*4+2];
                float4 d3 = sNb[wl][nb*4+3];
                float2 kf0 = ((const float2*)(Km + __float_as_int(d0.x)))[lane];
                float2 kf1 = ((const float2*)(Km + __float_as_int(d1.x)))[lane];
                float2 kf2 = ((const float2*)(Km + __float_as_int(d2.x)))[lane];
                float2 kf3 = ((const float2*)(Km + __float_as_int(d3.x)))[lane];
                float wv;
                wv = kf0.x + fmaf(d0.y,P00,fmaf(d0.z,P10,fmaf(d0.w,P20,qb0)));
                s0 += wv; q0 = fmaf(wv,wv,q0);
                wv = kf0.y + fmaf(d0.y,P01,fmaf(d0.z,P11,fmaf(d0.w,P21,qb1)));
                s1 += wv; q1 = fmaf(wv,wv,q1);
                wv = kf1.x + fmaf(d1.y,P00,fmaf(d1.z,P10,fmaf(d1.w,P20,qb0)));
                s0 += wv; q0 = fmaf(wv,wv,q0);
                wv = kf1.y + fmaf(d1.y,P01,fmaf(d1.z,P11,fmaf(d1.w,P21,qb1)));
                s1 += wv; q1 = fmaf(wv,wv,q1);
                wv = kf2.x + fmaf(d2.y,P00,fmaf(d2.z,P10,fmaf(d2.w,P20,qb0)));
                s0 += wv; q0 = fmaf(wv,wv,q0);
                wv = kf2.y + fmaf(d2.y,P01,fmaf(d2.z,P11,fmaf(d2.w,P21,qb1)));
                s1 += wv; q1 = fmaf(wv,wv,q1);
                wv = kf3.x + fmaf(d3.y,P00,fmaf(d3.z,P10,fmaf(d3.w,P20,qb0)));
                s0 += wv; q0 = fmaf(wv,wv,q0);
                wv = kf3.y + fmaf(d3.y,P01,fmaf(d3.z,P11,fmaf(d3.w,P21,qb1)));
                s1 += wv; q1 = fmaf(wv,wv,q1);
            }
            __syncwarp();
        }
        if (tid < 64) { sS[tid] = 0.f; sQ[tid] = 0.f; }
        __syncthreads();
        atomicAdd(&sS[ch0], s0); atomicAdd(&sQ[ch0], q0);
        atomicAdd(&sS[ch1], s1); atomicAdd(&sQ[ch1], q1);
        __syncthreads();
        if (tid < 64) {
            atomicAdd(&st[144 + tid], sS[tid]);
            atomicAdd(&st[208 + tid], sQ[tid]);
        }
    }
}

// ---------------------------------------------------------------------------
// pass B: recompute w, bnw1+relu -> smem stage -> GEMV 64->8, fused bnw2 stats
__global__ void __launch_bounds__(256, 5) k_passB(
        const int* __restrict__ knn,
        const float* __restrict__ Qm, const float* __restrict__ Km,
        const float4* __restrict__ U,
        const float* __restrict__ bnpg, const float* __restrict__ bnpb,
        const float* __restrict__ Wp2, const float* __restrict__ bp2,
        const float* __restrict__ g1, const float* __restrict__ b1,
        const float* __restrict__ Ww1, const float* __restrict__ bw1,
        float* __restrict__ w1out, float* __restrict__ st)
{
    __shared__ float sWw1[64][8];
    __shared__ float sBw[8];
    __shared__ float sWm[8][16][68];
    __shared__ float4 sNb[8][16];
    __shared__ float sS8[8], sQ8[8];
    const int tid = threadIdx.x, lane = tid & 31, wl = tid >> 5;
    for (int i = tid; i < 512; i += 256) sWw1[i >> 3][i & 7] = Ww1[i];
    if (tid < 8) { sBw[tid] = bw1[tid]; sS8[tid] = 0.f; sQ8[tid] = 0.f; }
    __syncthreads();
    const int ch0 = lane * 2, ch1 = ch0 + 1;
    float A0,A1,A2,C0,C1,C2; bnp_params(st, bnpg, bnpb, A0,A1,A2,C0,C1,C2);
    float P00=__ldg(&Wp2[ch0]), P10=__ldg(&Wp2[64+ch0]), P20=__ldg(&Wp2[128+ch0]), B0=__ldg(&bp2[ch0]);
    float P01=__ldg(&Wp2[ch1]), P11=__ldg(&Wp2[64+ch1]), P21=__ldg(&Wp2[128+ch1]), B1=__ldg(&bp2[ch1]);
    float m0 = __ldg(&st[144+ch0]) * INV_P;
    float Aa0 = __ldg(&g1[ch0]) * rsqrtf(fmaf(-m0, m0, __ldg(&st[208+ch0]) * INV_P) + EPSF);
    float Cc0 = fmaf(-m0, Aa0, __ldg(&b1[ch0]));
    float m1 = __ldg(&st[144+ch1]) * INV_P;
    float Aa1 = __ldg(&g1[ch1]) * rsqrtf(fmaf(-m1, m1, __ldg(&st[208+ch1]) * INV_P) + EPSF);
    float Cc1 = fmaf(-m1, Aa1, __ldg(&b1[ch1]));

    const int pair = lane >> 1, ob = (lane & 1) << 2;
    float sAcc[4] = {0,0,0,0}, qAcc[4] = {0,0,0,0};
    const int warp = (blockIdx.x * blockDim.x + tid) >> 5;
    const int nw = (gridDim.x * blockDim.x) >> 5;
    for (int n = warp; n < NPTS; n += nw) {
        float2 qv = ((const float2*)(Qm + (long)n*64))[lane];
        float qb0 = B0 - qv.x, qb1 = B1 - qv.y;
        stage_nb(sNb[wl], n, lane, knn, U, A0,A1,A2, C0,C1,C2);
#pragma unroll
        for (int nb = 0; nb < 4; nb++) {
            float4 d0 = sNb[wl][nb*4+0];
            float4 d1 = sNb[wl][nb*4+1];
            float4 d2 = sNb[wl][nb*4+2];
            float4 d3 = sNb[wl][nb*4+3];
            float2 kf0 = ((const float2*)(Km + __float_as_int(d0.x)))[lane];
            float2 kf1 = ((const float2*)(Km + __float_as_int(d1.x)))[lane];
            float2 kf2 = ((const float2*)(Km + __float_as_int(d2.x)))[lane];
            float2 kf3 = ((const float2*)(Km + __float_as_int(d3.x)))[lane];
            float2 rw;
            rw.x = fmaxf(fmaf(kf0.x + fmaf(d0.y,P00,fmaf(d0.z,P10,fmaf(d0.w,P20,qb0))), Aa0, Cc0), 0.f);
            rw.y = fmaxf(fmaf(kf0.y + fmaf(d0.y,P01,fmaf(d0.z,P11,fmaf(d0.w,P21,qb1))), Aa1, Cc1), 0.f);
            *(float2*)&sWm[wl][nb*4+0][ch0] = rw;
            rw.x = fmaxf(fmaf(kf1.x + fmaf(d1.y,P00,fmaf(d1.z,P10,fmaf(d1.w,P20,qb0))), Aa0, Cc0), 0.f);
            rw.y = fmaxf(fmaf(kf1.y + fmaf(d1.y,P01,fmaf(d1.z,P11,fmaf(d1.w,P21,qb1))), Aa1, Cc1), 0.f);
            *(float2*)&sWm[wl][nb*4+1][ch0] = rw;
            rw.x = fmaxf(fmaf(kf2.x + fmaf(d2.y,P00,fmaf(d2.z,P10,fmaf(d2.w,P20,qb0))), Aa0, Cc0), 0.f);
            rw.y = fmaxf(fmaf(kf2.y + fmaf(d2.y,P01,fmaf(d2.z,P11,fmaf(d2.w,P21,qb1))), Aa1, Cc1), 0.f);
            *(float2*)&sWm[wl][nb*4+2][ch0] = rw;
            rw.x = fmaxf(fmaf(kf3.x + fmaf(d3.y,P00,fmaf(d3.z,P10,fmaf(d3.w,P20,qb0))), Aa0, Cc0), 0.f);
            rw.y = fmaxf(fmaf(kf3.y + fmaf(d3.y,P01,fmaf(d3.z,P11,fmaf(d3.w,P21,qb1))), Aa1, Cc1), 0.f);
            *(float2*)&sWm[wl][nb*4+3][ch0] = rw;
        }
        __syncwarp();
        float a0=0.f, a1=0.f, a2=0.f, a3=0.f;
        const float* wrow = sWm[wl][pair];
#pragma unroll
        for (int c4 = 0; c4 < 16; c4++) {
            float4 wv = *(const float4*)&wrow[c4*4];
            float4 w0 = *(const float4*)&sWw1[c4*4+0][ob];
            float4 w1 = *(const float4*)&sWw1[c4*4+1][ob];
            float4 w2 = *(const float4*)&sWw1[c4*4+2][ob];
            float4 w3 = *(const float4*)&sWw1[c4*4+3][ob];
            a0 = fmaf(wv.x, w0.x, fmaf(wv.y, w1.x, fmaf(wv.z, w2.x, fmaf(wv.w, w3.x, a0))));
            a1 = fmaf(wv.x, w0.y, fmaf(wv.y, w1.y, fmaf(wv.z, w2.y, fmaf(wv.w, w3.y, a1))));
            a2 = fmaf(wv.x, w0.z, fmaf(wv.y, w1.z, fmaf(wv.z, w2.z, fmaf(wv.w, w3.z, a2))));
            a3 = fmaf(wv.x, w0.w, fmaf(wv.y, w1.w, fmaf(wv.z, w2.w, fmaf(wv.w, w3.w, a3))));
        }
        float4 t;
        t.x = a0 + sBw[ob+0]; t.y = a1 + sBw[ob+1];
        t.z = a2 + sBw[ob+2]; t.w = a3 + sBw[ob+3];
        ((float4*)(w1out + (long)n*128))[lane] = t;
        sAcc[0]+=t.x; qAcc[0]=fmaf(t.x,t.x,qAcc[0]);
        sAcc[1]+=t.y; qAcc[1]=fmaf(t.y,t.y,qAcc[1]);
        sAcc[2]+=t.z; qAcc[2]=fmaf(t.z,t.z,qAcc[2]);
        sAcc[3]+=t.w; qAcc[3]=fmaf(t.w,t.w,qAcc[3]);
        __syncwarp();
    }
#pragma unroll
    for (int off = 16; off >= 2; off >>= 1) {
#pragma unroll
        for (int j = 0; j < 4; j++) {
            sAcc[j] += __shfl_xor_sync(0xffffffffu, sAcc[j], off);
            qAcc[j] += __shfl_xor_sync(0xffffffffu, qAcc[j], off);
        }
    }
    if (lane < 2) {
#pragma unroll
        for (int j = 0; j < 4; j++) {
            atomicAdd(&sS8[ob + j], sAcc[j]);
            atomicAdd(&sQ8[ob + j], qAcc[j]);
        }
    }
    __syncthreads();
    if (tid < 8) {
        atomicAdd(&st[272 + tid], sS8[tid]);
        atomicAdd(&st[280 + tid], sQ8[tid]);
    }
}

// ---------------------------------------------------------------------------
// pass C: bnw2+relu -> logits -> softmax -> weighted (v_g+pe) agg, fused bn2 stats
__global__ void __launch_bounds__(256, 6) k_passC(
        const int* __restrict__ knn,
        const float* __restrict__ Vm, const float* __restrict__ w1in,
        const float4* __restrict__ U,
        const float* __restrict__ bnpg, const float* __restrict__ bnpb,
        const float* __restrict__ Wp2, const float* __restrict__ bp2,
        const float* __restrict__ g2, const float* __restrict__ b2,
        const float* __restrict__ Ww2, const float* __restrict__ bw2,
        float* __restrict__ agg, float* __restrict__ st)
{
    __shared__ float sW2[8][8];
    __shared__ float sA8[8], sC8[8], sB8[8];
    __shared__ float wsm[8][8][16];   // [warp][o][ns]
    __shared__ float4 sNb[8][16];
    __shared__ float sS[64], sQ[64];
    const int tid = threadIdx.x, lane = tid & 31, wl = tid >> 5;
    if (tid < 64) { sW2[tid >> 3][tid & 7] = Ww2[tid]; sS[tid] = 0.f; sQ[tid] = 0.f; }
    if (tid < 8) {
        float m = st[272 + tid] * INV_P;
        float var = fmaf(-m, m, st[280 + tid] * INV_P);
        float a = g2[tid] * rsqrtf(var + EPSF);
        sA8[tid] = a; sC8[tid] = fmaf(-m, a, b2[tid]);
        sB8[tid] = bw2[tid];
    }
    __syncthreads();
    const int c0 = lane, c1 = lane + 32;
    float A0,A1,A2,C0,C1,C2; bnp_params(st, bnpg, bnpb, A0,A1,A2,C0,C1,C2);
    float P00=__ldg(&Wp2[c0]), P10=__ldg(&Wp2[64+c0]), P20=__ldg(&Wp2[128+c0]), B0=__ldg(&bp2[c0]);
    float P01=__ldg(&Wp2[c1]), P11=__ldg(&Wp2[64+c1]), P21=__ldg(&Wp2[128+c1]), B1=__ldg(&bp2[c1]);
    const int pair = lane >> 1, ob = (lane & 1) << 2;
    const int oo = lane & 7;
    float s0=0,q0=0,s1=0,q1=0;
    const int warp = (blockIdx.x * blockDim.x + tid) >> 5;
    const int nw = (gridDim.x * blockDim.x) >> 5;
    for (int n = warp; n < NPTS; n += nw) {
        // phase 1: logits
        {
            const float4* wp = (const float4*)(w1in + (long)n*128 + pair*8);
            float4 lo = wp[0], hi = wp[1];
            float rv[8] = {lo.x, lo.y, lo.z, lo.w, hi.x, hi.y, hi.z, hi.w};
#pragma unroll
            for (int i = 0; i < 8; i++) rv[i] = fmaxf(fmaf(rv[i], sA8[i], sC8[i]), 0.f);
#pragma unroll
            for (int j = 0; j < 4; j++) {
                int o = ob + j;
                float lg = sB8[o];
#pragma unroll
                for (int i = 0; i < 8; i++) lg = fmaf(rv[i], sW2[i][o], lg);
                wsm[wl][o][pair] = lg;
            }
        }
        // stage neighbor data while logits settle
        stage_nb(sNb[wl], n, lane, knn, U, A0,A1,A2, C0,C1,C2);
        // phase 2: softmax over ns
        if (lane < 8) {
            float* row = wsm[wl][lane];
            float4 v0 = *(float4*)&row[0], v1 = *(float4*)&row[4];
            float4 v2 = *(float4*)&row[8], v3 = *(float4*)&row[12];
            float m = fmaxf(fmaxf(fmaxf(v0.x,v0.y),fmaxf(v0.z,v0.w)),
                     fmaxf(fmaxf(fmaxf(v1.x,v1.y),fmaxf(v1.z,v1.w)),
                     fmaxf(fmaxf(fmaxf(v2.x,v2.y),fmaxf(v2.z,v2.w)),
                           fmaxf(fmaxf(v3.x,v3.y),fmaxf(v3.z,v3.w)))));
            v0.x=__expf(v0.x-m); v0.y=__expf(v0.y-m); v0.z=__expf(v0.z-m); v0.w=__expf(v0.w-m);
            v1.x=__expf(v1.x-m); v1.y=__expf(v1.y-m); v1.z=__expf(v1.z-m); v1.w=__expf(v1.w-m);
            v2.x=__expf(v2.x-m); v2.y=__expf(v2.y-m); v2.z=__expf(v2.z-m); v2.w=__expf(v2.w-m);
            v3.x=__expf(v3.x-m); v3.y=__expf(v3.y-m); v3.z=__expf(v3.z-m); v3.w=__expf(v3.w-m);
            float ssum = (v0.x+v0.y+v0.z+v0.w)+(v1.x+v1.y+v1.z+v1.w)
                        +(v2.x+v2.y+v2.z+v2.w)+(v3.x+v3.y+v3.z+v3.w);
            float inv = 1.f / ssum;
            v0.x*=inv; v0.y*=inv; v0.z*=inv; v0.w*=inv;
            v1.x*=inv; v1.y*=inv; v1.z*=inv; v1.w*=inv;
            v2.x*=inv; v2.y*=inv; v2.z*=inv; v2.w*=inv;
            v3.x*=inv; v3.y*=inv; v3.z*=inv; v3.w*=inv;
            *(float4*)&row[0]=v0; *(float4*)&row[4]=v1;
            *(float4*)&row[8]=v2; *(float4*)&row[12]=v3;
        }
        __syncwarp();
        // phase 3: batched gather + weighted aggregation
        float acc0 = 0.f, acc1 = 0.f;
        const float* wrow = wsm[wl][oo];
#pragma unroll
        for (int nb = 0; nb < 4; nb++) {
            float4 d0 = sNb[wl][nb*4+0];
            float4 d1 = sNb[wl][nb*4+1];
            float4 d2 = sNb[wl][nb*4+2];
            float4 d3 = sNb[wl][nb*4+3];
            float4 wt = *(const float4*)&wrow[nb*4];
            int v0o = __float_as_int(d0.x);
            int v1o = __float_as_int(d1.x);
            int v2o = __float_as_int(d2.x);
            int v3o = __float_as_int(d3.x);
            float va0 = Vm[v0o+c0], vb0 = Vm[v0o+c1];
            float va1 = Vm[v1o+c0], vb1 = Vm[v1o+c1];
            float va2 = Vm[v2o+c0], vb2 = Vm[v2o+c1];
            float va3 = Vm[v3o+c0], vb3 = Vm[v3o+c1];
            acc0 = fmaf(va0 + fmaf(d0.y,P00,fmaf(d0.z,P10,fmaf(d0.w,P20,B0))), wt.x, acc0);
            acc1 = fmaf(vb0 + fmaf(d0.y,P01,fmaf(d0.z,P11,fmaf(d0.w,P21,B1))), wt.x, acc1);
            acc0 = fmaf(va1 + fmaf(d1.y,P00,fmaf(d1.z,P10,fmaf(d1.w,P20,B0))), wt.y, acc0);
            acc1 = fmaf(vb1 + fmaf(d1.y,P01,fmaf(d1.z,P11,fmaf(d1.w,P21,B1))), wt.y, acc1);
            acc0 = fmaf(va2 + fmaf(d2.y,P00,fmaf(d2.z,P10,fmaf(d2.w,P20,B0))), wt.z, acc0);
            acc1 = fmaf(vb2 + fmaf(d2.y,P01,fmaf(d2.z,P11,fmaf(d2.w,P21,B1))), wt.z, acc1);
            acc0 = fmaf(va3 + fmaf(d3.y,P00,fmaf(d3.z,P10,fmaf(d3.w,P20,B0))), wt.w, acc0);
            acc1 = fmaf(vb3 + fmaf(d3.y,P01,fmaf(d3.z,P11,fmaf(d3.w,P21,B1))), wt.w, acc1);
        }
        agg[(long)n*64 + c0] = acc0;
        agg[(long)n*64 + c1] = acc1;
        s0 += acc0; q0 = fmaf(acc0,acc0,q0);
        s1 += acc1; q1 = fmaf(acc1,acc1,q1);
        __syncwarp();
    }
    atomicAdd(&sS[c0], s0); atomicAdd(&sQ[c0], q0);
    atomicAdd(&sS[c1], s1); atomicAdd(&sQ[c1], q1);
    __syncthreads();
    if (tid < 64) {
        atomicAdd(&st[288 + tid], sS[tid]);
        atomicAdd(&st[352 + tid], sQ[tid]);
    }
}

// ---------------------------------------------------------------------------
// gemm3: t3 = relu(bn2(agg)) @ W3, fused bn3 stats
__global__ void __launch_bounds__(256) k_gemm3(
        const float* __restrict__ X, const float* __restrict__ W,
        const float* __restrict__ st, const float* __restrict__ bg,
        const float* __restrict__ bb, float* __restrict__ out, float* __restrict__ sto)
{
    __shared__ float sX[64][65];
    __shared__ float sW[64][64];
    __shared__ float sA[64], sC[64];
    __shared__ float sS[64], sQ[64];
    const int tid = threadIdx.x;
    const long row0 = (long)blockIdx.x * 64;
    if (tid < 64) {
        sS[tid] = 0.f; sQ[tid] = 0.f;
        float m = st[288 + tid] * INV_N;
        float var = fmaf(-m, m, st[352 + tid] * INV_N);
        float a = bg[tid] * rsqrtf(var + EPSF);
        sA[tid] = a; sC[tid] = fmaf(-m, a, bb[tid]);
    }
    for (int i = tid; i < 4096; i += 256) sW[i >> 6][i & 63] = W[i];
    __syncthreads();
    for (int i = tid; i < 4096; i += 256) {
        int r = i >> 6, kk = i & 63;
        sX[r][kk] = fmaxf(fmaf(X[(row0 + r) * 64 + kk], sA[kk], sC[kk]), 0.f);
    }
    __syncthreads();
    const int lane = tid & 31;
    const int r = tid & 63, c0 = (tid >> 6) << 4;
    float acc[16];
#pragma unroll
    for (int j = 0; j < 16; j++) acc[j] = 0.f;
#pragma unroll
    for (int kk = 0; kk < 64; kk++) {
        float xv = sX[r][kk];
#pragma unroll
        for (int j = 0; j < 16; j++) acc[j] = fmaf(xv, sW[kk][c0 + j], acc[j]);
    }
    float* op = out + (row0 + r) * 64 + c0;
#pragma unroll
    for (int j = 0; j < 16; j++) op[j] = acc[j];
#pragma unroll
    for (int j = 0; j < 16; j++) {
        float s = acc[j], q = acc[j] * acc[j];
#pragma unroll
        for (int off = 16; off; off >>= 1) {
            s += __shfl_xor_sync(0xffffffffu, s, off);
            q += __shfl_xor_sync(0xffffffffu, q, off);
        }
        if (lane == 0) { atomicAdd(&sS[c0 + j], s); atomicAdd(&sQ[c0 + j], q); }
    }
    __syncthreads();
    if (tid < 64) {
        atomicAdd(&sto[416 + tid], sS[tid]);
        atomicAdd(&sto[480 + tid], sQ[tid]);
    }
}

// out = relu(bn3(t3) + x), bn3 params inline
__global__ void k_final(const float* __restrict__ T3, const float* __restrict__ X,
                        const float* __restrict__ st,
                        const float* __restrict__ g3, const float* __restrict__ b3,
                        float* __restrict__ out)
{
    __shared__ float sA[64], sC[64];
    const int tid = threadIdx.x;
    if (tid < 64) {
        float m = st[416 + tid] * INV_N;
        float var = fmaf(-m, m, st[480 + tid] * INV_N);
        float a = g3[tid] * rsqrtf(var + EPSF);
        sA[tid] = a; sC[tid] = fmaf(-m, a, b3[tid]);
    }
    __syncthreads();
    const int stride = gridDim.x * blockDim.x;
    for (int i = blockIdx.x * blockDim.x + tid; i < NPTS * 16; i += stride) {
        int cb = (i * 4) & 63;
        float4 t = ((const float4*)T3)[i];
        float4 x4 = ((const float4*)X)[i];
        float4 r;
        r.x = fmaxf(fmaf(t.x, sA[cb+0], sC[cb+0]) + x4.x, 0.f);
        r.y = fmaxf(fmaf(t.y, sA[cb+1], sC[cb+1]) + x4.y, 0.f);
        r.z = fmaxf(fmaf(t.z, sA[cb+2], sC[cb+2]) + x4.z, 0.f);
        r.w = fmaxf(fmaf(t.w, sA[cb+3], sC[cb+3]) + x4.w, 0.f);
        ((float4*)out)[i] = r;
    }
}

// ---------------------------------------------------------------------------
extern "C" void kernel_launch(void* const* d_in, const int* in_sizes, int n_in,
                              void* d_out, int out_size)
{
    const float* p     = (const float*)d_in[0];
    const float* x     = (const float*)d_in[1];
    const int*   knn   = (const int*)  d_in[2];
    const float* W1    = (const float*)d_in[3];
    const float* bn1g  = (const float*)d_in[4];
    const float* bn1b  = (const float*)d_in[5];
    const float* Wq    = (const float*)d_in[6];
    const float* bq    = (const float*)d_in[7];
    const float* Wk    = (const float*)d_in[8];
    const float* bk    = (const float*)d_in[9];
    const float* Wv    = (const float*)d_in[10];
    const float* bv    = (const float*)d_in[11];
    const float* Wp1   = (const float*)d_in[12];
    const float* bp1   = (const float*)d_in[13];
    const float* bnpg  = (const float*)d_in[14];
    const float* bnpb  = (const float*)d_in[15];
    const float* Wp2   = (const float*)d_in[16];
    const float* bp2   = (const float*)d_in[17];
    const float* bnw1g = (const float*)d_in[18];
    const float* bnw1b = (const float*)d_in[19];
    const float* Ww1   = (const float*)d_in[20];
    const float* bw1   = (const float*)d_in[21];
    const float* bnw2g = (const float*)d_in[22];
    const float* bnw2b = (const float*)d_in[23];
    const float* Ww2   = (const float*)d_in[24];
    const float* bw2   = (const float*)d_in[25];
    const float* bn2g  = (const float*)d_in[26];
    const float* bn2b  = (const float*)d_in[27];
    const float* W3    = (const float*)d_in[28];
    const float* bn3g  = (const float*)d_in[29];
    const float* bn3b  = (const float*)d_in[30];
    float* out = (float*)d_out;

    float* scr = nullptr;
    cudaGetSymbolAddress((void**)&scr, g_scr);
    float* t1  = scr + OFF_T1;
    float* qb  = scr + OFF_Q;
    float* kb  = scr + OFF_K;
    float* vb  = scr + OFF_V;
    float* w1b = scr + OFF_W1B;
    float* agg = scr + OFF_AGG;
    float* t3  = scr + OFF_T3;
    float4* U  = (float4*)(scr + OFF_U);
    float* st  = scr + OFF_STATS;

    k_zero<<<1, 544>>>(st);

    // gemm1 + pstats (heterogeneous grid, overlapped)
    k_g1p<<<GEMM_BLOCKS + PST_BLOCKS, 256>>>(x, W1, t1, st, p, knn, Wp1, bp1, U);

    // q,k (bn1 inline, fused 2-GEMM loop)
    k_qk<<<GEMM_BLOCKS, 256>>>(t1, Wq, bq, Wk, bk, st, bn1g, bn1b, qb, kb);

    // v GEMM + bnw1 stats (heterogeneous, overlapped)
    k_vws<<<GEMM_BLOCKS + WS_BLOCKS, 256>>>(t1, Wv, bv, bn1g, bn1b, vb,
                                            knn, qb, kb, U, bnpg, bnpb, Wp2, bp2, st);

    // pass B (+ bnw2 stats)
    k_passB<<<740, 256>>>(knn, qb, kb, U, bnpg, bnpb, Wp2, bp2,
                          bnw1g, bnw1b, Ww1, bw1, w1b, st);

    // pass C (+ bn2 stats)
    k_passC<<<888, 256>>>(knn, vb, w1b, U, bnpg, bnpb, Wp2, bp2,
                          bnw2g, bnw2b, Ww2, bw2, agg, st);

    // gemm3 (bn2 inline, + bn3 stats)
    k_gemm3<<<1250, 256>>>(agg, W3, st, bn2g, bn2b, t3, st);

    // residual + relu (bn3 inline)
    k_final<<<640, 256>>>(t3, x, st, bn3g, bn3b, out);
}

// round 7
// speedup vs baseline: 1.0225x; 1.0225x over previous
#include <cuda_runtime.h>

#define NPTS 80000
#define NSAMP 16
#define PAIRS (NPTS*NSAMP)
#define EPSF 1e-5f
#define INV_N (1.0f/80000.0f)
#define INV_P (1.0f/1280000.0f)
#define GEMM_BLOCKS 1250
#define PST_BLOCKS  1024

// ---------------- scratch (device-global) ----------------
#define OFF_T1    0
#define OFF_Q     5120000
#define OFF_K     10240000
#define OFF_V     15360000
#define OFF_W1B   20480000
#define OFF_AGG   30720000
#define OFF_T3    35840000
#define OFF_U     40960000           /* float4 per pair: u0,u1,u2,pad */
#define OFF_STATS 46080000
__device__ float g_scr[46080640];

// stats sublayout:
//  +0   bn1 sum(64)   | +64  bn1 sq(64)
//  +128 bnp sum(3)    | +136 bnp sq(3)
//  +144 bnw1 sum(64)  | +208 bnw1 sq(64)
//  +272 bnw2 sum(8)   | +280 bnw2 sq(8)
//  +288 bn2 sum(64)   | +352 bn2 sq(64)
//  +416 bn3 sum(64)   | +480 bn3 sq(64)

__global__ void k_zero(float* st) { int i = threadIdx.x; if (i < 544) st[i] = 0.f; }

// ---------------------------------------------------------------------------
// heterogeneous: blocks [0,1250) = gemm1 (t1 = x@W1, fused bn1 stats);
//                blocks [1250,2274) = pstats (+ u store)
__global__ void __launch_bounds__(256) k_g1p(
        const float* __restrict__ X, const float* __restrict__ W,
        float* __restrict__ out, float* __restrict__ st,
        const float* __restrict__ p, const int* __restrict__ knn,
        const float* __restrict__ Wp1, const float* __restrict__ bp1,
        float4* __restrict__ U)
{
    const int tid = threadIdx.x;
    if (blockIdx.x < GEMM_BLOCKS) {
        __shared__ float sX[64][65];
        __shared__ float sW[64][64];
        __shared__ float sS[64], sQ[64];
        const long row0 = (long)blockIdx.x * 64;
        if (tid < 64) { sS[tid] = 0.f; sQ[tid] = 0.f; }
        for (int i = tid; i < 4096; i += 256) sW[i >> 6][i & 63] = W[i];
        for (int i = tid; i < 4096; i += 256) {
            int r = i >> 6, kk = i & 63;
            sX[r][kk] = X[(row0 + r) * 64 + kk];
        }
        __syncthreads();
        const int lane = tid & 31;
        const int r = tid & 63, c0 = (tid >> 6) << 4;
        float acc[16];
#pragma unroll
        for (int j = 0; j < 16; j++) acc[j] = 0.f;
#pragma unroll
        for (int kk = 0; kk < 64; kk++) {
            float xv = sX[r][kk];
#pragma unroll
            for (int j = 0; j < 16; j++) acc[j] = fmaf(xv, sW[kk][c0 + j], acc[j]);
        }
        float* op = out + (row0 + r) * 64 + c0;
#pragma unroll
        for (int j = 0; j < 16; j++) op[j] = acc[j];
#pragma unroll
        for (int j = 0; j < 16; j++) {
            float s = acc[j], q = acc[j] * acc[j];
#pragma unroll
            for (int off = 16; off; off >>= 1) {
                s += __shfl_xor_sync(0xffffffffu, s, off);
                q += __shfl_xor_sync(0xffffffffu, q, off);
            }
            if (lane == 0) { atomicAdd(&sS[c0 + j], s); atomicAdd(&sQ[c0 + j], q); }
        }
        __syncthreads();
        if (tid < 64) {
            atomicAdd(&st[tid], sS[tid]);
            atomicAdd(&st[64 + tid], sQ[tid]);
        }
    } else {
        float w[9], bb[3];
#pragma unroll
        for (int i = 0; i < 9; i++) w[i] = __ldg(&Wp1[i]);
#pragma unroll
        for (int j = 0; j < 3; j++) bb[j] = __ldg(&bp1[j]);
        float s0=0,s1=0,s2=0,q0=0,q1=0,q2=0;
        const int bid = blockIdx.x - GEMM_BLOCKS;
        const int stride = PST_BLOCKS * 256;
        for (int pr = bid * 256 + tid; pr < PAIRS; pr += stride) {
            int n = pr >> 4;
            int idx = __ldg(&knn[pr]);
            float ax = p[idx*3+0]-p[n*3+0];
            float ay = p[idx*3+1]-p[n*3+1];
            float az = p[idx*3+2]-p[n*3+2];
            float u0 = fmaf(ax,w[0],fmaf(ay,w[3],fmaf(az,w[6],bb[0])));
            float u1 = fmaf(ax,w[1],fmaf(ay,w[4],fmaf(az,w[7],bb[1])));
            float u2 = fmaf(ax,w[2],fmaf(ay,w[5],fmaf(az,w[8],bb[2])));
            U[pr] = make_float4(u0, u1, u2, 0.f);
            s0+=u0; s1+=u1; s2+=u2;
            q0=fmaf(u0,u0,q0); q1=fmaf(u1,u1,q1); q2=fmaf(u2,u2,q2);
        }
#pragma unroll
        for (int off = 16; off; off >>= 1) {
            s0 += __shfl_xor_sync(0xffffffffu, s0, off);
            s1 += __shfl_xor_sync(0xffffffffu, s1, off);
            s2 += __shfl_xor_sync(0xffffffffu, s2, off);
            q0 += __shfl_xor_sync(0xffffffffu, q0, off);
            q1 += __shfl_xor_sync(0xffffffffu, q1, off);
            q2 += __shfl_xor_sync(0xffffffffu, q2, off);
        }
        __shared__ float sm[6];
        if (tid < 6) sm[tid] = 0.f;
        __syncthreads();
        if ((tid & 31) == 0) {
            atomicAdd(&sm[0], s0); atomicAdd(&sm[1], s1); atomicAdd(&sm[2], s2);
            atomicAdd(&sm[3], q0); atomicAdd(&sm[4], q1); atomicAdd(&sm[5], q2);
        }
        __syncthreads();
        if (tid < 3) {
            atomicAdd(&st[128 + tid], sm[tid]);
            atomicAdd(&st[136 + tid], sm[3 + tid]);
        }
    }
}

// q/k/v fused: one t1 tile load (+bn1), three weight matrices looped through smem
__global__ void __launch_bounds__(256) k_qkv(
        const float* __restrict__ T1,
        const float* __restrict__ Wq, const float* __restrict__ bq,
        const float* __restrict__ Wk, const float* __restrict__ bk,
        const float* __restrict__ Wv, const float* __restrict__ bv,
        const float* __restrict__ st,
        const float* __restrict__ g1, const float* __restrict__ b1,
        float* __restrict__ oq, float* __restrict__ ok, float* __restrict__ ov)
{
    __shared__ float sX[64][65];
    __shared__ float sW[64][64];
    __shared__ float sA[64], sC[64];
    const int tid = threadIdx.x;
    const long row0 = (long)blockIdx.x * 64;
    if (tid < 64) {
        float m = st[tid] * INV_N;
        float var = fmaf(-m, m, st[64 + tid] * INV_N);
        float a = g1[tid] * rsqrtf(var + EPSF);
        sA[tid] = a; sC[tid] = fmaf(-m, a, b1[tid]);
    }
    __syncthreads();
    for (int i = tid; i < 4096; i += 256) {
        int r = i >> 6, kk = i & 63;
        sX[r][kk] = fmaxf(fmaf(T1[(row0 + r) * 64 + kk], sA[kk], sC[kk]), 0.f);
    }
    const int r = tid & 63, c0 = (tid >> 6) << 4;
    const float* Ws[3] = {Wq, Wk, Wv};
    const float* Bs[3] = {bq, bk, bv};
    float* Os[3] = {oq, ok, ov};
#pragma unroll 1
    for (int m = 0; m < 3; m++) {
        __syncthreads();
        for (int i = tid; i < 4096; i += 256) sW[i >> 6][i & 63] = Ws[m][i];
        __syncthreads();
        float acc[16];
#pragma unroll
        for (int j = 0; j < 16; j++) acc[j] = __ldg(&Bs[m][c0 + j]);
#pragma unroll
        for (int kk = 0; kk < 64; kk++) {
            float xv = sX[r][kk];
#pragma unroll
            for (int j = 0; j < 16; j++) acc[j] = fmaf(xv, sW[kk][c0 + j], acc[j]);
        }
        float* op = Os[m] + (row0 + r) * 64 + c0;
#pragma unroll
        for (int j = 0; j < 16; j++) op[j] = acc[j];
    }
}

// ---------------------------------------------------------------------------
__device__ __forceinline__ void bnp_params(const float* st, const float* bnpg,
                                           const float* bnpb,
                                           float& A0, float& A1, float& A2,
                                           float& C0, float& C1, float& C2)
{
    float m0 = __ldg(&st[128]) * INV_P;
    A0 = __ldg(&bnpg[0]) * rsqrtf(fmaf(-m0, m0, __ldg(&st[136]) * INV_P) + EPSF);
    C0 = fmaf(-m0, A0, __ldg(&bnpb[0]));
    float m1 = __ldg(&st[129]) * INV_P;
    A1 = __ldg(&bnpg[1]) * rsqrtf(fmaf(-m1, m1, __ldg(&st[137]) * INV_P) + EPSF);
    C1 = fmaf(-m1, A1, __ldg(&bnpb[1]));
    float m2 = __ldg(&st[130]) * INV_P;
    A2 = __ldg(&bnpg[2]) * rsqrtf(fmaf(-m2, m2, __ldg(&st[138]) * INV_P) + EPSF);
    C2 = fmaf(-m2, A2, __ldg(&bnpb[2]));
}

// stage (idx*64, relu(bn(u))) for 16 neighbors of point n into smem (lanes 0..15)
__device__ __forceinline__ void stage_nb(float4* row, int n, int lane,
                                         const int* __restrict__ knn,
                                         const float4* __restrict__ U,
                                         float A0, float A1, float A2,
                                         float C0, float C1, float C2)
{
    if (lane < 16) {
        int mk = __ldg(&knn[n*16 + lane]) << 6;   // element offset into 64-ch rows
        float4 uu = __ldg(&U[n*16 + lane]);
        float t0 = fmaxf(fmaf(uu.x, A0, C0), 0.f);
        float t1 = fmaxf(fmaf(uu.y, A1, C1), 0.f);
        float t2 = fmaxf(fmaf(uu.z, A2, C2), 0.f);
        row[lane] = make_float4(__int_as_float(mk), t0, t1, t2);
    }
    __syncwarp();
}

// ---------------------------------------------------------------------------
// pass A: stats of w = k_g - q + pe. warp-per-point, float2 channels (2l,2l+1).
__global__ void __launch_bounds__(256, 6) k_wstats(
        const int* __restrict__ knn,
        const float* __restrict__ Qm, const float* __restrict__ Km,
        const float4* __restrict__ U,
        const float* __restrict__ bnpg, const float* __restrict__ bnpb,
        const float* __restrict__ Wp2, const float* __restrict__ bp2,
        float* __restrict__ st)
{
    __shared__ float4 sNb[8][16];
    const int tid = threadIdx.x, lane = tid & 31, wl = tid >> 5;
    const int ch0 = lane * 2, ch1 = ch0 + 1;
    float A0,A1,A2,C0,C1,C2; bnp_params(st, bnpg, bnpb, A0,A1,A2,C0,C1,C2);
    float P00=__ldg(&Wp2[ch0]), P10=__ldg(&Wp2[64+ch0]), P20=__ldg(&Wp2[128+ch0]), B0=__ldg(&bp2[ch0]);
    float P01=__ldg(&Wp2[ch1]), P11=__ldg(&Wp2[64+ch1]), P21=__ldg(&Wp2[128+ch1]), B1=__ldg(&bp2[ch1]);
    float s0=0,q0=0,s1=0,q1=0;
    const int warp = (blockIdx.x * blockDim.x + tid) >> 5;
    const int nw = (gridDim.x * blockDim.x) >> 5;
    for (int n = warp; n < NPTS; n += nw) {
        float2 qv = ((const float2*)(Qm + (long)n*64))[lane];
        float qb0 = B0 - qv.x, qb1 = B1 - qv.y;
        stage_nb(sNb[wl], n, lane, knn, U, A0,A1,A2, C0,C1,C2);
#pragma unroll
        for (int nb = 0; nb < 4; nb++) {
            float4 d0 = sNb[wl][nb*4+0];
            float4 d1 = sNb[wl][nb*4+1];
            float4 d2 = sNb[wl][nb*4+2];
            float4 d3 = sNb[wl][nb*4+3];
            float2 kf0 = ((const float2*)(Km + __float_as_int(d0.x)))[lane];
            float2 kf1 = ((const float2*)(Km + __float_as_int(d1.x)))[lane];
            float2 kf2 = ((const float2*)(Km + __float_as_int(d2.x)))[lane];
            float2 kf3 = ((const float2*)(Km + __float_as_int(d3.x)))[lane];
            float wv;
            wv = kf0.x + fmaf(d0.y,P00,fmaf(d0.z,P10,fmaf(d0.w,P20,qb0)));
            s0 += wv; q0 = fmaf(wv,wv,q0);
            wv = kf0.y + fmaf(d0.y,P01,fmaf(d0.z,P11,fmaf(d0.w,P21,qb1)));
            s1 += wv; q1 = fmaf(wv,wv,q1);
            wv = kf1.x + fmaf(d1.y,P00,fmaf(d1.z,P10,fmaf(d1.w,P20,qb0)));
            s0 += wv; q0 = fmaf(wv,wv,q0);
            wv = kf1.y + fmaf(d1.y,P01,fmaf(d1.z,P11,fmaf(d1.w,P21,qb1)));
            s1 += wv; q1 = fmaf(wv,wv,q1);
            wv = kf2.x + fmaf(d2.y,P00,fmaf(d2.z,P10,fmaf(d2.w,P20,qb0)));
            s0 += wv; q0 = fmaf(wv,wv,q0);
            wv = kf2.y + fmaf(d2.y,P01,fmaf(d2.z,P11,fmaf(d2.w,P21,qb1)));
            s1 += wv; q1 = fmaf(wv,wv,q1);
            wv = kf3.x + fmaf(d3.y,P00,fmaf(d3.z,P10,fmaf(d3.w,P20,qb0)));
            s0 += wv; q0 = fmaf(wv,wv,q0);
            wv = kf3.y + fmaf(d3.y,P01,fmaf(d3.z,P11,fmaf(d3.w,P21,qb1)));
            s1 += wv; q1 = fmaf(wv,wv,q1);
        }
        __syncwarp();
    }
    __shared__ float sS[64], sQ[64];
    if (tid < 64) { sS[tid] = 0.f; sQ[tid] = 0.f; }
    __syncthreads();
    atomicAdd(&sS[ch0], s0); atomicAdd(&sQ[ch0], q0);
    atomicAdd(&sS[ch1], s1); atomicAdd(&sQ[ch1], q1);
    __syncthreads();
    if (tid < 64) {
        atomicAdd(&st[144 + tid], sS[tid]);
        atomicAdd(&st[208 + tid], sQ[tid]);
    }
}

// ---------------------------------------------------------------------------
// pass B: recompute w, bnw1+relu -> smem stage -> GEMV 64->8, fused bnw2 stats
__global__ void __launch_bounds__(256, 5) k_passB(
        const int* __restrict__ knn,
        const float* __restrict__ Qm, const float* __restrict__ Km,
        const float4* __restrict__ U,
        const float* __restrict__ bnpg, const float* __restrict__ bnpb,
        const float* __restrict__ Wp2, const float* __restrict__ bp2,
        const float* __restrict__ g1, const float* __restrict__ b1,
        const float* __restrict__ Ww1, const float* __restrict__ bw1,
        float* __restrict__ w1out, float* __restrict__ st)
{
    __shared__ float sWw1[64][8];
    __shared__ float sBw[8];
    __shared__ float sWm[8][16][68];
    __shared__ float4 sNb[8][16];
    __shared__ float sS8[8], sQ8[8];
    const int tid = threadIdx.x, lane = tid & 31, wl = tid >> 5;
    for (int i = tid; i < 512; i += 256) sWw1[i >> 3][i & 7] = Ww1[i];
    if (tid < 8) { sBw[tid] = bw1[tid]; sS8[tid] = 0.f; sQ8[tid] = 0.f; }
    __syncthreads();
    const int ch0 = lane * 2, ch1 = ch0 + 1;
    float A0,A1,A2,C0,C1,C2; bnp_params(st, bnpg, bnpb, A0,A1,A2,C0,C1,C2);
    float P00=__ldg(&Wp2[ch0]), P10=__ldg(&Wp2[64+ch0]), P20=__ldg(&Wp2[128+ch0]), B0=__ldg(&bp2[ch0]);
    float P01=__ldg(&Wp2[ch1]), P11=__ldg(&Wp2[64+ch1]), P21=__ldg(&Wp2[128+ch1]), B1=__ldg(&bp2[ch1]);
    float m0 = __ldg(&st[144+ch0]) * INV_P;
    float Aa0 = __ldg(&g1[ch0]) * rsqrtf(fmaf(-m0, m0, __ldg(&st[208+ch0]) * INV_P) + EPSF);
    float Cc0 = fmaf(-m0, Aa0, __ldg(&b1[ch0]));
    float m1 = __ldg(&st[144+ch1]) * INV_P;
    float Aa1 = __ldg(&g1[ch1]) * rsqrtf(fmaf(-m1, m1, __ldg(&st[208+ch1]) * INV_P) + EPSF);
    float Cc1 = fmaf(-m1, Aa1, __ldg(&b1[ch1]));

    const int pair = lane >> 1, ob = (lane & 1) << 2;
    float sAcc[4] = {0,0,0,0}, qAcc[4] = {0,0,0,0};
    const int warp = (blockIdx.x * blockDim.x + tid) >> 5;
    const int nw = (gridDim.x * blockDim.x) >> 5;
    for (int n = warp; n < NPTS; n += nw) {
        float2 qv = ((const float2*)(Qm + (long)n*64))[lane];
        float qb0 = B0 - qv.x, qb1 = B1 - qv.y;
        stage_nb(sNb[wl], n, lane, knn, U, A0,A1,A2, C0,C1,C2);
#pragma unroll
        for (int nb = 0; nb < 4; nb++) {
            float4 d0 = sNb[wl][nb*4+0];
            float4 d1 = sNb[wl][nb*4+1];
            float4 d2 = sNb[wl][nb*4+2];
            float4 d3 = sNb[wl][nb*4+3];
            float2 kf0 = ((const float2*)(Km + __float_as_int(d0.x)))[lane];
            float2 kf1 = ((const float2*)(Km + __float_as_int(d1.x)))[lane];
            float2 kf2 = ((const float2*)(Km + __float_as_int(d2.x)))[lane];
            float2 kf3 = ((const float2*)(Km + __float_as_int(d3.x)))[lane];
            float2 rw;
            rw.x = fmaxf(fmaf(kf0.x + fmaf(d0.y,P00,fmaf(d0.z,P10,fmaf(d0.w,P20,qb0))), Aa0, Cc0), 0.f);
            rw.y = fmaxf(fmaf(kf0.y + fmaf(d0.y,P01,fmaf(d0.z,P11,fmaf(d0.w,P21,qb1))), Aa1, Cc1), 0.f);
            *(float2*)&sWm[wl][nb*4+0][ch0] = rw;
            rw.x = fmaxf(fmaf(kf1.x + fmaf(d1.y,P00,fmaf(d1.z,P10,fmaf(d1.w,P20,qb0))), Aa0, Cc0), 0.f);
            rw.y = fmaxf(fmaf(kf1.y + fmaf(d1.y,P01,fmaf(d1.z,P11,fmaf(d1.w,P21,qb1))), Aa1, Cc1), 0.f);
            *(float2*)&sWm[wl][nb*4+1][ch0] = rw;
            rw.x = fmaxf(fmaf(kf2.x + fmaf(d2.y,P00,fmaf(d2.z,P10,fmaf(d2.w,P20,qb0))), Aa0, Cc0), 0.f);
            rw.y = fmaxf(fmaf(kf2.y + fmaf(d2.y,P01,fmaf(d2.z,P11,fmaf(d2.w,P21,qb1))), Aa1, Cc1), 0.f);
            *(float2*)&sWm[wl][nb*4+2][ch0] = rw;
            rw.x = fmaxf(fmaf(kf3.x + fmaf(d3.y,P00,fmaf(d3.z,P10,fmaf(d3.w,P20,qb0))), Aa0, Cc0), 0.f);
            rw.y = fmaxf(fmaf(kf3.y + fmaf(d3.y,P01,fmaf(d3.z,P11,fmaf(d3.w,P21,qb1))), Aa1, Cc1), 0.f);
            *(float2*)&sWm[wl][nb*4+3][ch0] = rw;
        }
        __syncwarp();
        float a0=0.f, a1=0.f, a2=0.f, a3=0.f;
        const float* wrow = sWm[wl][pair];
#pragma unroll
        for (int c4 = 0; c4 < 16; c4++) {
            float4 wv = *(const float4*)&wrow[c4*4];
            float4 w0 = *(const float4*)&sWw1[c4*4+0][ob];
            float4 w1 = *(const float4*)&sWw1[c4*4+1][ob];
            float4 w2 = *(const float4*)&sWw1[c4*4+2][ob];
            float4 w3 = *(const float4*)&sWw1[c4*4+3][ob];
            a0 = fmaf(wv.x, w0.x, fmaf(wv.y, w1.x, fmaf(wv.z, w2.x, fmaf(wv.w, w3.x, a0))));
            a1 = fmaf(wv.x, w0.y, fmaf(wv.y, w1.y, fmaf(wv.z, w2.y, fmaf(wv.w, w3.y, a1))));
            a2 = fmaf(wv.x, w0.z, fmaf(wv.y, w1.z, fmaf(wv.z, w2.z, fmaf(wv.w, w3.z, a2))));
            a3 = fmaf(wv.x, w0.w, fmaf(wv.y, w1.w, fmaf(wv.z, w2.w, fmaf(wv.w, w3.w, a3))));
        }
        float4 t;
        t.x = a0 + sBw[ob+0]; t.y = a1 + sBw[ob+1];
        t.z = a2 + sBw[ob+2]; t.w = a3 + sBw[ob+3];
        ((float4*)(w1out + (long)n*128))[lane] = t;
        sAcc[0]+=t.x; qAcc[0]=fmaf(t.x,t.x,qAcc[0]);
        sAcc[1]+=t.y; qAcc[1]=fmaf(t.y,t.y,qAcc[1]);
        sAcc[2]+=t.z; qAcc[2]=fmaf(t.z,t.z,qAcc[2]);
        sAcc[3]+=t.w; qAcc[3]=fmaf(t.w,t.w,qAcc[3]);
        __syncwarp();
    }
#pragma unroll
    for (int off = 16; off >= 2; off >>= 1) {
#pragma unroll
        for (int j = 0; j < 4; j++) {
            sAcc[j] += __shfl_xor_sync(0xffffffffu, sAcc[j], off);
            qAcc[j] += __shfl_xor_sync(0xffffffffu, qAcc[j], off);
        }
    }
    if (lane < 2) {
#pragma unroll
        for (int j = 0; j < 4; j++) {
            atomicAdd(&sS8[ob + j], sAcc[j]);
            atomicAdd(&sQ8[ob + j], qAcc[j]);
        }
    }
    __syncthreads();
    if (tid < 8) {
        atomicAdd(&st[272 + tid], sS8[tid]);
        atomicAdd(&st[280 + tid], sQ8[tid]);
    }
}

// ---------------------------------------------------------------------------
// pass C: bnw2+relu -> logits -> softmax -> weighted (v_g+pe) agg, fused bn2 stats
__global__ void __launch_bounds__(256, 6) k_passC(
        const int* __restrict__ knn,
        const float* __restrict__ Vm, const float* __restrict__ w1in,
        const float4* __restrict__ U,
        const float* __restrict__ bnpg, const float* __restrict__ bnpb,
        const float* __restrict__ Wp2, const float* __restrict__ bp2,
        const float* __restrict__ g2, const float* __restrict__ b2,
        const float* __restrict__ Ww2, const float* __restrict__ bw2,
        float* __restrict__ agg, float* __restrict__ st)
{
    __shared__ float sW2[8][8];
    __shared__ float sA8[8], sC8[8], sB8[8];
    __shared__ float wsm[8][8][16];   // [warp][o][ns]
    __shared__ float4 sNb[8][16];
    __shared__ float sS[64], sQ[64];
    const int tid = threadIdx.x, lane = tid & 31, wl = tid >> 5;
    if (tid < 64) { sW2[tid >> 3][tid & 7] = Ww2[tid]; sS[tid] = 0.f; sQ[tid] = 0.f; }
    if (tid < 8) {
        float m = st[272 + tid] * INV_P;
        float var = fmaf(-m, m, st[280 + tid] * INV_P);
        float a = g2[tid] * rsqrtf(var + EPSF);
        sA8[tid] = a; sC8[tid] = fmaf(-m, a, b2[tid]);
        sB8[tid] = bw2[tid];
    }
    __syncthreads();
    const int c0 = lane, c1 = lane + 32;
    float A0,A1,A2,C0,C1,C2; bnp_params(st, bnpg, bnpb, A0,A1,A2,C0,C1,C2);
    float P00=__ldg(&Wp2[c0]), P10=__ldg(&Wp2[64+c0]), P20=__ldg(&Wp2[128+c0]), B0=__ldg(&bp2[c0]);
    float P01=__ldg(&Wp2[c1]), P11=__ldg(&Wp2[64+c1]), P21=__ldg(&Wp2[128+c1]), B1=__ldg(&bp2[c1]);
    const int pair = lane >> 1, ob = (lane & 1) << 2;
    const int oo = lane & 7;
    float s0=0,q0=0,s1=0,q1=0;
    const int warp = (blockIdx.x * blockDim.x + tid) >> 5;
    const int nw = (gridDim.x * blockDim.x) >> 5;
    for (int n = warp; n < NPTS; n += nw) {
        // phase 1: logits
        {
            const float4* wp = (const float4*)(w1in + (long)n*128 + pair*8);
            float4 lo = wp[0], hi = wp[1];
            float rv[8] = {lo.x, lo.y, lo.z, lo.w, hi.x, hi.y, hi.z, hi.w};
#pragma unroll
            for (int i = 0; i < 8; i++) rv[i] = fmaxf(fmaf(rv[i], sA8[i], sC8[i]), 0.f);
#pragma unroll
            for (int j = 0; j < 4; j++) {
                int o = ob + j;
                float lg = sB8[o];
#pragma unroll
                for (int i = 0; i < 8; i++) lg = fmaf(rv[i], sW2[i][o], lg);
                wsm[wl][o][pair] = lg;
            }
        }
        // stage neighbor data while logits settle
        stage_nb(sNb[wl], n, lane, knn, U, A0,A1,A2, C0,C1,C2);
        // phase 2: softmax over ns
        if (lane < 8) {
            float* row = wsm[wl][lane];
            float4 v0 = *(float4*)&row[0], v1 = *(float4*)&row[4];
            float4 v2 = *(float4*)&row[8], v3 = *(float4*)&row[12];
            float m = fmaxf(fmaxf(fmaxf(v0.x,v0.y),fmaxf(v0.z,v0.w)),
                     fmaxf(fmaxf(fmaxf(v1.x,v1.y),fmaxf(v1.z,v1.w)),
                     fmaxf(fmaxf(fmaxf(v2.x,v2.y),fmaxf(v2.z,v2.w)),
                           fmaxf(fmaxf(v3.x,v3.y),fmaxf(v3.z,v3.w)))));
            v0.x=__expf(v0.x-m); v0.y=__expf(v0.y-m); v0.z=__expf(v0.z-m); v0.w=__expf(v0.w-m);
            v1.x=__expf(v1.x-m); v1.y=__expf(v1.y-m); v1.z=__expf(v1.z-m); v1.w=__expf(v1.w-m);
            v2.x=__expf(v2.x-m); v2.y=__expf(v2.y-m); v2.z=__expf(v2.z-m); v2.w=__expf(v2.w-m);
            v3.x=__expf(v3.x-m); v3.y=__expf(v3.y-m); v3.z=__expf(v3.z-m); v3.w=__expf(v3.w-m);
            float ssum = (v0.x+v0.y+v0.z+v0.w)+(v1.x+v1.y+v1.z+v1.w)
                        +(v2.x+v2.y+v2.z+v2.w)+(v3.x+v3.y+v3.z+v3.w);
            float inv = 1.f / ssum;
            v0.x*=inv; v0.y*=inv; v0.z*=inv; v0.w*=inv;
            v1.x*=inv; v1.y*=inv; v1.z*=inv; v1.w*=inv;
            v2.x*=inv; v2.y*=inv; v2.z*=inv; v2.w*=inv;
            v3.x*=inv; v3.y*=inv; v3.z*=inv; v3.w*=inv;
            *(float4*)&row[0]=v0; *(float4*)&row[4]=v1;
            *(float4*)&row[8]=v2; *(float4*)&row[12]=v3;
        }
        __syncwarp();
        // phase 3: batched gather + weighted aggregation
        float acc0 = 0.f, acc1 = 0.f;
        const float* wrow = wsm[wl][oo];
#pragma unroll
        for (int nb = 0; nb < 4; nb++) {
            float4 d0 = sNb[wl][nb*4+0];
            float4 d1 = sNb[wl][nb*4+1];
            float4 d2 = sNb[wl][nb*4+2];
            float4 d3 = sNb[wl][nb*4+3];
            float4 wt = *(const float4*)&wrow[nb*4];
            int v0o = __float_as_int(d0.x);
            int v1o = __float_as_int(d1.x);
            int v2o = __float_as_int(d2.x);
            int v3o = __float_as_int(d3.x);
            float va0 = Vm[v0o+c0], vb0 = Vm[v0o+c1];
            float va1 = Vm[v1o+c0], vb1 = Vm[v1o+c1];
            float va2 = Vm[v2o+c0], vb2 = Vm[v2o+c1];
            float va3 = Vm[v3o+c0], vb3 = Vm[v3o+c1];
            acc0 = fmaf(va0 + fmaf(d0.y,P00,fmaf(d0.z,P10,fmaf(d0.w,P20,B0))), wt.x, acc0);
            acc1 = fmaf(vb0 + fmaf(d0.y,P01,fmaf(d0.z,P11,fmaf(d0.w,P21,B1))), wt.x, acc1);
            acc0 = fmaf(va1 + fmaf(d1.y,P00,fmaf(d1.z,P10,fmaf(d1.w,P20,B0))), wt.y, acc0);
            acc1 = fmaf(vb1 + fmaf(d1.y,P01,fmaf(d1.z,P11,fmaf(d1.w,P21,B1))), wt.y, acc1);
            acc0 = fmaf(va2 + fmaf(d2.y,P00,fmaf(d2.z,P10,fmaf(d2.w,P20,B0))), wt.z, acc0);
            acc1 = fmaf(vb2 + fmaf(d2.y,P01,fmaf(d2.z,P11,fmaf(d2.w,P21,B1))), wt.z, acc1);
            acc0 = fmaf(va3 + fmaf(d3.y,P00,fmaf(d3.z,P10,fmaf(d3.w,P20,B0))), wt.w, acc0);
            acc1 = fmaf(vb3 + fmaf(d3.y,P01,fmaf(d3.z,P11,fmaf(d3.w,P21,B1))), wt.w, acc1);
        }
        agg[(long)n*64 + c0] = acc0;
        agg[(long)n*64 + c1] = acc1;
        s0 += acc0; q0 = fmaf(acc0,acc0,q0);
        s1 += acc1; q1 = fmaf(acc1,acc1,q1);
        __syncwarp();
    }
    atomicAdd(&sS[c0], s0); atomicAdd(&sQ[c0], q0);
    atomicAdd(&sS[c1], s1); atomicAdd(&sQ[c1], q1);
    __syncthreads();
    if (tid < 64) {
        atomicAdd(&st[288 + tid], sS[tid]);
        atomicAdd(&st[352 + tid], sQ[tid]);
    }
}

// ---------------------------------------------------------------------------
// gemm3: t3 = relu(bn2(agg)) @ W3, fused bn3 stats
__global__ void __launch_bounds__(256) k_gemm3(
        const float* __restrict__ X, const float* __restrict__ W,
        const float* __restrict__ st, const float* __restrict__ bg,
        const float* __restrict__ bb, float* __restrict__ out, float* __restrict__ sto)
{
    __shared__ float sX[64][65];
    __shared__ float sW[64][64];
    __shared__ float sA[64], sC[64];
    __shared__ float sS[64], sQ[64];
    const int tid = threadIdx.x;
    const long row0 = (long)blockIdx.x * 64;
    if (tid < 64) {
        sS[tid] = 0.f; sQ[tid] = 0.f;
        float m = st[288 + tid] * INV_N;
        float var = fmaf(-m, m, st[352 + tid] * INV_N);
        float a = bg[tid] * rsqrtf(var + EPSF);
        sA[tid] = a; sC[tid] = fmaf(-m, a, bb[tid]);
    }
    for (int i = tid; i < 4096; i += 256) sW[i >> 6][i & 63] = W[i];
    __syncthreads();
    for (int i = tid; i < 4096; i += 256) {
        int r = i >> 6, kk = i & 63;
        sX[r][kk] = fmaxf(fmaf(X[(row0 + r) * 64 + kk], sA[kk], sC[kk]), 0.f);
    }
    __syncthreads();
    const int lane = tid & 31;
    const int r = tid & 63, c0 = (tid >> 6) << 4;
    float acc[16];
#pragma unroll
    for (int j = 0; j < 16; j++) acc[j] = 0.f;
#pragma unroll
    for (int kk = 0; kk < 64; kk++) {
        float xv = sX[r][kk];
#pragma unroll
        for (int j = 0; j < 16; j++) acc[j] = fmaf(xv, sW[kk][c0 + j], acc[j]);
    }
    float* op = out + (row0 + r) * 64 + c0;
#pragma unroll
    for (int j = 0; j < 16; j++) op[j] = acc[j];
#pragma unroll
    for (int j = 0; j < 16; j++) {
        float s = acc[j], q = acc[j] * acc[j];
#pragma unroll
        for (int off = 16; off; off >>= 1) {
            s += __shfl_xor_sync(0xffffffffu, s, off);
            q += __shfl_xor_sync(0xffffffffu, q, off);
        }
        if (lane == 0) { atomicAdd(&sS[c0 + j], s); atomicAdd(&sQ[c0 + j], q); }
    }
    __syncthreads();
    if (tid < 64) {
        atomicAdd(&sto[416 + tid], sS[tid]);
        atomicAdd(&sto[480 + tid], sQ[tid]);
    }
}

// out = relu(bn3(t3) + x), bn3 params inline
__global__ void k_final(const float* __restrict__ T3, const float* __restrict__ X,
                        const float* __restrict__ st,
                        const float* __restrict__ g3, const float* __restrict__ b3,
                        float* __restrict__ out)
{
    __shared__ float sA[64], sC[64];
    const int tid = threadIdx.x;
    if (tid < 64) {
        float m = st[416 + tid] * INV_N;
        float var = fmaf(-m, m, st[480 + tid] * INV_N);
        float a = g3[tid] * rsqrtf(var + EPSF);
        sA[tid] = a; sC[tid] = fmaf(-m, a, b3[tid]);
    }
    __syncthreads();
    const int stride = gridDim.x * blockDim.x;
    for (int i = blockIdx.x * blockDim.x + tid; i < NPTS * 16; i += stride) {
        int cb = (i * 4) & 63;
        float4 t = ((const float4*)T3)[i];
        float4 x4 = ((const float4*)X)[i];
        float4 r;
        r.x = fmaxf(fmaf(t.x, sA[cb+0], sC[cb+0]) + x4.x, 0.f);
        r.y = fmaxf(fmaf(t.y, sA[cb+1], sC[cb+1]) + x4.y, 0.f);
        r.z = fmaxf(fmaf(t.z, sA[cb+2], sC[cb+2]) + x4.z, 0.f);
        r.w = fmaxf(fmaf(t.w, sA[cb+3], sC[cb+3]) + x4.w, 0.f);
        ((float4*)out)[i] = r;
    }
}

// ---------------------------------------------------------------------------
extern "C" void kernel_launch(void* const* d_in, const int* in_sizes, int n_in,
                              void* d_out, int out_size)
{
    const float* p     = (const float*)d_in[0];
    const float* x     = (const float*)d_in[1];
    const int*   knn   = (const int*)  d_in[2];
    const float* W1    = (const float*)d_in[3];
    const float* bn1g  = (const float*)d_in[4];
    const float* bn1b  = (const float*)d_in[5];
    const float* Wq    = (const float*)d_in[6];
    const float* bq    = (const float*)d_in[7];
    const float* Wk    = (const float*)d_in[8];
    const float* bk    = (const float*)d_in[9];
    const float* Wv    = (const float*)d_in[10];
    const float* bv    = (const float*)d_in[11];
    const float* Wp1   = (const float*)d_in[12];
    const float* bp1   = (const float*)d_in[13];
    const float* bnpg  = (const float*)d_in[14];
    const float* bnpb  = (const float*)d_in[15];
    const float* Wp2   = (const float*)d_in[16];
    const float* bp2   = (const float*)d_in[17];
    const float* bnw1g = (const float*)d_in[18];
    const float* bnw1b = (const float*)d_in[19];
    const float* Ww1   = (const float*)d_in[20];
    const float* bw1   = (const float*)d_in[21];
    const float* bnw2g = (const float*)d_in[22];
    const float* bnw2b = (const float*)d_in[23];
    const float* Ww2   = (const float*)d_in[24];
    const float* bw2   = (const float*)d_in[25];
    const float* bn2g  = (const float*)d_in[26];
    const float* bn2b  = (const float*)d_in[27];
    const float* W3    = (const float*)d_in[28];
    const float* bn3g  = (const float*)d_in[29];
    const float* bn3b  = (const float*)d_in[30];
    float* out = (float*)d_out;

    float* scr = nullptr;
    cudaGetSymbolAddress((void**)&scr, g_scr);
    float* t1  = scr + OFF_T1;
    float* qb  = scr + OFF_Q;
    float* kb  = scr + OFF_K;
    float* vb  = scr + OFF_V;
    float* w1b = scr + OFF_W1B;
    float* agg = scr + OFF_AGG;
    float* t3  = scr + OFF_T3;
    float4* U  = (float4*)(scr + OFF_U);
    float* st  = scr + OFF_STATS;

    k_zero<<<1, 544>>>(st);

    // gemm1 + pstats (heterogeneous grid, overlapped)
    k_g1p<<<GEMM_BLOCKS + PST_BLOCKS, 256>>>(x, W1, t1, st, p, knn, Wp1, bp1, U);

    // q,k,v (bn1 inline, fused 3-GEMM loop)
    k_qkv<<<GEMM_BLOCKS, 256>>>(t1, Wq, bq, Wk, bk, Wv, bv, st, bn1g, bn1b, qb, kb, vb);

    // bnw1 stats (exact wave: 148 SM x 6 blocks)
    k_wstats<<<888, 256>>>(knn, qb, kb, U, bnpg, bnpb, Wp2, bp2, st);

    // pass B (+ bnw2 stats) — exact wave at 5 blocks/SM
    k_passB<<<740, 256>>>(knn, qb, kb, U, bnpg, bnpb, Wp2, bp2,
                          bnw1g, bnw1b, Ww1, bw1, w1b, st);

    // pass C (+ bn2 stats)
    k_passC<<<888, 256>>>(knn, vb, w1b, U, bnpg, bnpb, Wp2, bp2,
                          bnw2g, bnw2b, Ww2, bw2, agg, st);

    // gemm3 (bn2 inline, + bn3 stats)
    k_gemm3<<<1250, 256>>>(agg, W3, st, bn2g, bn2b, t3, st);

    // residual + relu (bn3 inline)
    k_final<<<640, 256>>>(t3, x, st, bn3g, bn3b, out);
}

// round 8
// speedup vs baseline: 1.0842x; 1.0604x over previous
#include <cuda_runtime.h>

#define NPTS 80000
#define NSAMP 16
#define PAIRS (NPTS*NSAMP)
#define EPSF 1e-5f
#define INV_N (1.0f/80000.0f)
#define INV_P (1.0f/1280000.0f)
#define GEMM_BLOCKS 1250
#define PST_BLOCKS  1024

// ---------------- scratch (device-global) ----------------
#define OFF_T1    0
#define OFF_Q     5120000
#define OFF_K     10240000
#define OFF_V     15360000
#define OFF_W1B   20480000
#define OFF_AGG   30720000
#define OFF_T3    35840000
#define OFF_U     40960000           /* float4 per pair: u0,u1,u2,pad */
#define OFF_STATS 46080000
__device__ float g_scr[46080640];

// stats sublayout:
//  +0   bn1 sum(64)   | +64  bn1 sq(64)
//  +128 bnp sum(3)    | +136 bnp sq(3)
//  +144 bnw1 sum(64)  | +208 bnw1 sq(64)
//  +272 bnw2 sum(8)   | +280 bnw2 sq(8)
//  +288 bn2 sum(64)   | +352 bn2 sq(64)
//  +416 bn3 sum(64)   | +480 bn3 sq(64)

__global__ void k_zero(float* st) { int i = threadIdx.x; if (i < 544) st[i] = 0.f; }

// ---------------------------------------------------------------------------
// heterogeneous: blocks [0,1250) = gemm1 (t1 = x@W1, fused bn1 stats);
//                blocks [1250,2274) = pstats (+ u store)
__global__ void __launch_bounds__(256) k_g1p(
        const float* __restrict__ X, const float* __restrict__ W,
        float* __restrict__ out, float* __restrict__ st,
        const float* __restrict__ p, const int* __restrict__ knn,
        const float* __restrict__ Wp1, const float* __restrict__ bp1,
        float4* __restrict__ U)
{
    const int tid = threadIdx.x;
    if (blockIdx.x < GEMM_BLOCKS) {
        __shared__ float sX[64][65];
        __shared__ float sW[64][64];
        __shared__ float sS[64], sQ[64];
        const long row0 = (long)blockIdx.x * 64;
        if (tid < 64) { sS[tid] = 0.f; sQ[tid] = 0.f; }
        for (int i = tid; i < 4096; i += 256) sW[i >> 6][i & 63] = W[i];
        for (int i = tid; i < 4096; i += 256) {
            int r = i >> 6, kk = i & 63;
            sX[r][kk] = X[(row0 + r) * 64 + kk];
        }
        __syncthreads();
        const int lane = tid & 31;
        const int r = tid & 63, c0 = (tid >> 6) << 4;
        float acc[16];
#pragma unroll
        for (int j = 0; j < 16; j++) acc[j] = 0.f;
#pragma unroll
        for (int kk = 0; kk < 64; kk++) {
            float xv = sX[r][kk];
#pragma unroll
            for (int j = 0; j < 16; j++) acc[j] = fmaf(xv, sW[kk][c0 + j], acc[j]);
        }
        float* op = out + (row0 + r) * 64 + c0;
#pragma unroll
        for (int j = 0; j < 16; j++) op[j] = acc[j];
#pragma unroll
        for (int j = 0; j < 16; j++) {
            float s = acc[j], q = acc[j] * acc[j];
#pragma unroll
            for (int off = 16; off; off >>= 1) {
                s += __shfl_xor_sync(0xffffffffu, s, off);
                q += __shfl_xor_sync(0xffffffffu, q, off);
            }
            if (lane == 0) { atomicAdd(&sS[c0 + j], s); atomicAdd(&sQ[c0 + j], q); }
        }
        __syncthreads();
        if (tid < 64) {
            atomicAdd(&st[tid], sS[tid]);
            atomicAdd(&st[64 + tid], sQ[tid]);
        }
    } else {
        float w[9], bb[3];
#pragma unroll
        for (int i = 0; i < 9; i++) w[i] = __ldg(&Wp1[i]);
#pragma unroll
        for (int j = 0; j < 3; j++) bb[j] = __ldg(&bp1[j]);
        float s0=0,s1=0,s2=0,q0=0,q1=0,q2=0;
        const int bid = blockIdx.x - GEMM_BLOCKS;
        const int stride = PST_BLOCKS * 256;
        for (int pr = bid * 256 + tid; pr < PAIRS; pr += stride) {
            int n = pr >> 4;
            int idx = __ldg(&knn[pr]);
            float ax = p[idx*3+0]-p[n*3+0];
            float ay = p[idx*3+1]-p[n*3+1];
            float az = p[idx*3+2]-p[n*3+2];
            float u0 = fmaf(ax,w[0],fmaf(ay,w[3],fmaf(az,w[6],bb[0])));
            float u1 = fmaf(ax,w[1],fmaf(ay,w[4],fmaf(az,w[7],bb[1])));
            float u2 = fmaf(ax,w[2],fmaf(ay,w[5],fmaf(az,w[8],bb[2])));
            U[pr] = make_float4(u0, u1, u2, 0.f);
            s0+=u0; s1+=u1; s2+=u2;
            q0=fmaf(u0,u0,q0); q1=fmaf(u1,u1,q1); q2=fmaf(u2,u2,q2);
        }
#pragma unroll
        for (int off = 16; off; off >>= 1) {
            s0 += __shfl_xor_sync(0xffffffffu, s0, off);
            s1 += __shfl_xor_sync(0xffffffffu, s1, off);
            s2 += __shfl_xor_sync(0xffffffffu, s2, off);
            q0 += __shfl_xor_sync(0xffffffffu, q0, off);
            q1 += __shfl_xor_sync(0xffffffffu, q1, off);
            q2 += __shfl_xor_sync(0xffffffffu, q2, off);
        }
        __shared__ float sm[6];
        if (tid < 6) sm[tid] = 0.f;
        __syncthreads();
        if ((tid & 31) == 0) {
            atomicAdd(&sm[0], s0); atomicAdd(&sm[1], s1); atomicAdd(&sm[2], s2);
            atomicAdd(&sm[3], q0); atomicAdd(&sm[4], q1); atomicAdd(&sm[5], q2);
        }
        __syncthreads();
        if (tid < 3) {
            atomicAdd(&st[128 + tid], sm[tid]);
            atomicAdd(&st[136 + tid], sm[3 + tid]);
        }
    }
}

// q/k/v fused: one t1 tile load (+bn1), three weight matrices looped through smem
__global__ void __launch_bounds__(256) k_qkv(
        const float* __restrict__ T1,
        const float* __restrict__ Wq, const float* __restrict__ bq,
        const float* __restrict__ Wk, const float* __restrict__ bk,
        const float* __restrict__ Wv, const float* __restrict__ bv,
        const float* __restrict__ st,
        const float* __restrict__ g1, const float* __restrict__ b1,
        float* __restrict__ oq, float* __restrict__ ok, float* __restrict__ ov)
{
    __shared__ float sX[64][65];
    __shared__ float sW[64][64];
    __shared__ float sA[64], sC[64];
    const int tid = threadIdx.x;
    const long row0 = (long)blockIdx.x * 64;
    if (tid < 64) {
        float m = st[tid] * INV_N;
        float var = fmaf(-m, m, st[64 + tid] * INV_N);
        float a = g1[tid] * rsqrtf(var + EPSF);
        sA[tid] = a; sC[tid] = fmaf(-m, a, b1[tid]);
    }
    __syncthreads();
    for (int i = tid; i < 4096; i += 256) {
        int r = i >> 6, kk = i & 63;
        sX[r][kk] = fmaxf(fmaf(T1[(row0 + r) * 64 + kk], sA[kk], sC[kk]), 0.f);
    }
    const int r = tid & 63, c0 = (tid >> 6) << 4;
    const float* Ws[3] = {Wq, Wk, Wv};
    const float* Bs[3] = {bq, bk, bv};
    float* Os[3] = {oq, ok, ov};
#pragma unroll 1
    for (int m = 0; m < 3; m++) {
        __syncthreads();
        for (int i = tid; i < 4096; i += 256) sW[i >> 6][i & 63] = Ws[m][i];
        __syncthreads();
        float acc[16];
#pragma unroll
        for (int j = 0; j < 16; j++) acc[j] = __ldg(&Bs[m][c0 + j]);
#pragma unroll
        for (int kk = 0; kk < 64; kk++) {
            float xv = sX[r][kk];
#pragma unroll
            for (int j = 0; j < 16; j++) acc[j] = fmaf(xv, sW[kk][c0 + j], acc[j]);
        }
        float* op = Os[m] + (row0 + r) * 64 + c0;
#pragma unroll
        for (int j = 0; j < 16; j++) op[j] = acc[j];
    }
}

// ---------------------------------------------------------------------------
__device__ __forceinline__ void bnp_params(const float* st, const float* bnpg,
                                           const float* bnpb,
                                           float& A0, float& A1, float& A2,
                                           float& C0, float& C1, float& C2)
{
    float m0 = __ldg(&st[128]) * INV_P;
    A0 = __ldg(&bnpg[0]) * rsqrtf(fmaf(-m0, m0, __ldg(&st[136]) * INV_P) + EPSF);
    C0 = fmaf(-m0, A0, __ldg(&bnpb[0]));
    float m1 = __ldg(&st[129]) * INV_P;
    A1 = __ldg(&bnpg[1]) * rsqrtf(fmaf(-m1, m1, __ldg(&st[137]) * INV_P) + EPSF);
    C1 = fmaf(-m1, A1, __ldg(&bnpb[1]));
    float m2 = __ldg(&st[130]) * INV_P;
    A2 = __ldg(&bnpg[2]) * rsqrtf(fmaf(-m2, m2, __ldg(&st[138]) * INV_P) + EPSF);
    C2 = fmaf(-m2, A2, __ldg(&bnpb[2]));
}

// stage (idx*64, relu(bn(u))) for 16 neighbors of point n into smem (lanes 0..15)
__device__ __forceinline__ void stage_nb(float4* row, int n, int lane,
                                         const int* __restrict__ knn,
                                         const float4* __restrict__ U,
                                         float A0, float A1, float A2,
                                         float C0, float C1, float C2)
{
    if (lane < 16) {
        int mk = __ldg(&knn[n*16 + lane]) << 6;   // element offset into 64-ch rows
        float4 uu = __ldg(&U[n*16 + lane]);
        float t0 = fmaxf(fmaf(uu.x, A0, C0), 0.f);
        float t1 = fmaxf(fmaf(uu.y, A1, C1), 0.f);
        float t2 = fmaxf(fmaf(uu.z, A2, C2), 0.f);
        row[lane] = make_float4(__int_as_float(mk), t0, t1, t2);
    }
    __syncwarp();
}

// ---------------------------------------------------------------------------
// pass A: stats of w = k_g - q + pe. warp-per-point, float2 channels (2l,2l+1).
__global__ void __launch_bounds__(256, 6) k_wstats(
        const int* __restrict__ knn,
        const float* __restrict__ Qm, const float* __restrict__ Km,
        const float4* __restrict__ U,
        const float* __restrict__ bnpg, const float* __restrict__ bnpb,
        const float* __restrict__ Wp2, const float* __restrict__ bp2,
        float* __restrict__ st)
{
    __shared__ float4 sNb[8][16];
    const int tid = threadIdx.x, lane = tid & 31, wl = tid >> 5;
    const int ch0 = lane * 2, ch1 = ch0 + 1;
    float A0,A1,A2,C0,C1,C2; bnp_params(st, bnpg, bnpb, A0,A1,A2,C0,C1,C2);
    float P00=__ldg(&Wp2[ch0]), P10=__ldg(&Wp2[64+ch0]), P20=__ldg(&Wp2[128+ch0]), B0=__ldg(&bp2[ch0]);
    float P01=__ldg(&Wp2[ch1]), P11=__ldg(&Wp2[64+ch1]), P21=__ldg(&Wp2[128+ch1]), B1=__ldg(&bp2[ch1]);
    float s0=0,q0=0,s1=0,q1=0;
    const int warp = (blockIdx.x * blockDim.x + tid) >> 5;
    const int nw = (gridDim.x * blockDim.x) >> 5;
    for (int n = warp; n < NPTS; n += nw) {
        float2 qv = ((const float2*)(Qm + (long)n*64))[lane];
        float qb0 = B0 - qv.x, qb1 = B1 - qv.y;
        stage_nb(sNb[wl], n, lane, knn, U, A0,A1,A2, C0,C1,C2);
#pragma unroll
        for (int nb = 0; nb < 4; nb++) {
            float4 d0 = sNb[wl][nb*4+0];
            float4 d1 = sNb[wl][nb*4+1];
            float4 d2 = sNb[wl][nb*4+2];
            float4 d3 = sNb[wl][nb*4+3];
            float2 kf0 = ((const float2*)(Km + __float_as_int(d0.x)))[lane];
            float2 kf1 = ((const float2*)(Km + __float_as_int(d1.x)))[lane];
            float2 kf2 = ((const float2*)(Km + __float_as_int(d2.x)))[lane];
            float2 kf3 = ((const float2*)(Km + __float_as_int(d3.x)))[lane];
            float wv;
            wv = kf0.x + fmaf(d0.y,P00,fmaf(d0.z,P10,fmaf(d0.w,P20,qb0)));
            s0 += wv; q0 = fmaf(wv,wv,q0);
            wv = kf0.y + fmaf(d0.y,P01,fmaf(d0.z,P11,fmaf(d0.w,P21,qb1)));
            s1 += wv; q1 = fmaf(wv,wv,q1);
            wv = kf1.x + fmaf(d1.y,P00,fmaf(d1.z,P10,fmaf(d1.w,P20,qb0)));
            s0 += wv; q0 = fmaf(wv,wv,q0);
            wv = kf1.y + fmaf(d1.y,P01,fmaf(d1.z,P11,fmaf(d1.w,P21,qb1)));
            s1 += wv; q1 = fmaf(wv,wv,q1);
            wv = kf2.x + fmaf(d2.y,P00,fmaf(d2.z,P10,fmaf(d2.w,P20,qb0)));
            s0 += wv; q0 = fmaf(wv,wv,q0);
            wv = kf2.y + fmaf(d2.y,P01,fmaf(d2.z,P11,fmaf(d2.w,P21,qb1)));
            s1 += wv; q1 = fmaf(wv,wv,q1);
            wv = kf3.x + fmaf(d3.y,P00,fmaf(d3.z,P10,fmaf(d3.w,P20,qb0)));
            s0 += wv; q0 = fmaf(wv,wv,q0);
            wv = kf3.y + fmaf(d3.y,P01,fmaf(d3.z,P11,fmaf(d3.w,P21,qb1)));
            s1 += wv; q1 = fmaf(wv,wv,q1);
        }
        __syncwarp();
    }
    __shared__ float sS[64], sQ[64];
    if (tid < 64) { sS[tid] = 0.f; sQ[tid] = 0.f; }
    __syncthreads();
    atomicAdd(&sS[ch0], s0); atomicAdd(&sQ[ch0], q0);
    atomicAdd(&sS[ch1], s1); atomicAdd(&sQ[ch1], q1);
    __syncthreads();
    if (tid < 64) {
        atomicAdd(&st[144 + tid], sS[tid]);
        atomicAdd(&st[208 + tid], sQ[tid]);
    }
}

// ---------------------------------------------------------------------------
// pass B: recompute w, bnw1+relu -> smem stage -> GEMV 64->8, fused bnw2 stats
// (R4-measured configuration: no occupancy clamp)
__global__ void __launch_bounds__(256) k_passB(
        const int* __restrict__ knn,
        const float* __restrict__ Qm, const float* __restrict__ Km,
        const float4* __restrict__ U,
        const float* __restrict__ bnpg, const float* __restrict__ bnpb,
        const float* __restrict__ Wp2, const float* __restrict__ bp2,
        const float* __restrict__ g1, const float* __restrict__ b1,
        const float* __restrict__ Ww1, const float* __restrict__ bw1,
        float* __restrict__ w1out, float* __restrict__ st)
{
    __shared__ float sWw1[64][8];
    __shared__ float sBw[8];
    __shared__ float sWm[8][16][68];
    __shared__ float4 sNb[8][16];
    __shared__ float sS8[8], sQ8[8];
    const int tid = threadIdx.x, lane = tid & 31, wl = tid >> 5;
    for (int i = tid; i < 512; i += 256) sWw1[i >> 3][i & 7] = Ww1[i];
    if (tid < 8) { sBw[tid] = bw1[tid]; sS8[tid] = 0.f; sQ8[tid] = 0.f; }
    __syncthreads();
    const int ch0 = lane * 2, ch1 = ch0 + 1;
    float A0,A1,A2,C0,C1,C2; bnp_params(st, bnpg, bnpb, A0,A1,A2,C0,C1,C2);
    float P00=__ldg(&Wp2[ch0]), P10=__ldg(&Wp2[64+ch0]), P20=__ldg(&Wp2[128+ch0]), B0=__ldg(&bp2[ch0]);
    float P01=__ldg(&Wp2[ch1]), P11=__ldg(&Wp2[64+ch1]), P21=__ldg(&Wp2[128+ch1]), B1=__ldg(&bp2[ch1]);
    float m0 = __ldg(&st[144+ch0]) * INV_P;
    float Aa0 = __ldg(&g1[ch0]) * rsqrtf(fmaf(-m0, m0, __ldg(&st[208+ch0]) * INV_P) + EPSF);
    float Cc0 = fmaf(-m0, Aa0, __ldg(&b1[ch0]));
    float m1 = __ldg(&st[144+ch1]) * INV_P;
    float Aa1 = __ldg(&g1[ch1]) * rsqrtf(fmaf(-m1, m1, __ldg(&st[208+ch1]) * INV_P) + EPSF);
    float Cc1 = fmaf(-m1, Aa1, __ldg(&b1[ch1]));

    const int pair = lane >> 1, ob = (lane & 1) << 2;
    float sAcc[4] = {0,0,0,0}, qAcc[4] = {0,0,0,0};
    const int warp = (blockIdx.x * blockDim.x + tid) >> 5;
    const int nw = (gridDim.x * blockDim.x) >> 5;
    for (int n = warp; n < NPTS; n += nw) {
        float2 qv = ((const float2*)(Qm + (long)n*64))[lane];
        float qb0 = B0 - qv.x, qb1 = B1 - qv.y;
        stage_nb(sNb[wl], n, lane, knn, U, A0,A1,A2, C0,C1,C2);
#pragma unroll
        for (int nb = 0; nb < 4; nb++) {
            float4 d0 = sNb[wl][nb*4+0];
            float4 d1 = sNb[wl][nb*4+1];
            float4 d2 = sNb[wl][nb*4+2];
            float4 d3 = sNb[wl][nb*4+3];
            float2 kf0 = ((const float2*)(Km + __float_as_int(d0.x)))[lane];
            float2 kf1 = ((const float2*)(Km + __float_as_int(d1.x)))[lane];
            float2 kf2 = ((const float2*)(Km + __float_as_int(d2.x)))[lane];
            float2 kf3 = ((const float2*)(Km + __float_as_int(d3.x)))[lane];
            float2 rw;
            rw.x = fmaxf(fmaf(kf0.x + fmaf(d0.y,P00,fmaf(d0.z,P10,fmaf(d0.w,P20,qb0))), Aa0, Cc0), 0.f);
            rw.y = fmaxf(fmaf(kf0.y + fmaf(d0.y,P01,fmaf(d0.z,P11,fmaf(d0.w,P21,qb1))), Aa1, Cc1), 0.f);
            *(float2*)&sWm[wl][nb*4+0][ch0] = rw;
            rw.x = fmaxf(fmaf(kf1.x + fmaf(d1.y,P00,fmaf(d1.z,P10,fmaf(d1.w,P20,qb0))), Aa0, Cc0), 0.f);
            rw.y = fmaxf(fmaf(kf1.y + fmaf(d1.y,P01,fmaf(d1.z,P11,fmaf(d1.w,P21,qb1))), Aa1, Cc1), 0.f);
            *(float2*)&sWm[wl][nb*4+1][ch0] = rw;
            rw.x = fmaxf(fmaf(kf2.x + fmaf(d2.y,P00,fmaf(d2.z,P10,fmaf(d2.w,P20,qb0))), Aa0, Cc0), 0.f);
            rw.y = fmaxf(fmaf(kf2.y + fmaf(d2.y,P01,fmaf(d2.z,P11,fmaf(d2.w,P21,qb1))), Aa1, Cc1), 0.f);
            *(float2*)&sWm[wl][nb*4+2][ch0] = rw;
            rw.x = fmaxf(fmaf(kf3.x + fmaf(d3.y,P00,fmaf(d3.z,P10,fmaf(d3.w,P20,qb0))), Aa0, Cc0), 0.f);
            rw.y = fmaxf(fmaf(kf3.y + fmaf(d3.y,P01,fmaf(d3.z,P11,fmaf(d3.w,P21,qb1))), Aa1, Cc1), 0.f);
            *(float2*)&sWm[wl][nb*4+3][ch0] = rw;
        }
        __syncwarp();
        float a0=0.f, a1=0.f, a2=0.f, a3=0.f;
        const float* wrow = sWm[wl][pair];
#pragma unroll
        for (int c4 = 0; c4 < 16; c4++) {
            float4 wv = *(const float4*)&wrow[c4*4];
            float4 w0 = *(const float4*)&sWw1[c4*4+0][ob];
            float4 w1 = *(const float4*)&sWw1[c4*4+1][ob];
            float4 w2 = *(const float4*)&sWw1[c4*4+2][ob];
            float4 w3 = *(const float4*)&sWw1[c4*4+3][ob];
            a0 = fmaf(wv.x, w0.x, fmaf(wv.y, w1.x, fmaf(wv.z, w2.x, fmaf(wv.w, w3.x, a0))));
            a1 = fmaf(wv.x, w0.y, fmaf(wv.y, w1.y, fmaf(wv.z, w2.y, fmaf(wv.w, w3.y, a1))));
            a2 = fmaf(wv.x, w0.z, fmaf(wv.y, w1.z, fmaf(wv.z, w2.z, fmaf(wv.w, w3.z, a2))));
            a3 = fmaf(wv.x, w0.w, fmaf(wv.y, w1.w, fmaf(wv.z, w2.w, fmaf(wv.w, w3.w, a3))));
        }
        float4 t;
        t.x = a0 + sBw[ob+0]; t.y = a1 + sBw[ob+1];
        t.z = a2 + sBw[ob+2]; t.w = a3 + sBw[ob+3];
        ((float4*)(w1out + (long)n*128))[lane] = t;
        sAcc[0]+=t.x; qAcc[0]=fmaf(t.x,t.x,qAcc[0]);
        sAcc[1]+=t.y; qAcc[1]=fmaf(t.y,t.y,qAcc[1]);
        sAcc[2]+=t.z; qAcc[2]=fmaf(t.z,t.z,qAcc[2]);
        sAcc[3]+=t.w; qAcc[3]=fmaf(t.w,t.w,qAcc[3]);
        __syncwarp();
    }
#pragma unroll
    for (int off = 16; off >= 2; off >>= 1) {
#pragma unroll
        for (int j = 0; j < 4; j++) {
            sAcc[j] += __shfl_xor_sync(0xffffffffu, sAcc[j], off);
            qAcc[j] += __shfl_xor_sync(0xffffffffu, qAcc[j], off);
        }
    }
    if (lane < 2) {
#pragma unroll
        for (int j = 0; j < 4; j++) {
            atomicAdd(&sS8[ob + j], sAcc[j]);
            atomicAdd(&sQ8[ob + j], qAcc[j]);
        }
    }
    __syncthreads();
    if (tid < 8) {
        atomicAdd(&st[272 + tid], sS8[tid]);
        atomicAdd(&st[280 + tid], sQ8[tid]);
    }
}

// ---------------------------------------------------------------------------
// pass C: bnw2+relu -> logits -> softmax -> weighted (v_g+pe) agg, fused bn2 stats
// (R4-measured configuration: no occupancy clamp)
__global__ void __launch_bounds__(256) k_passC(
        const int* __restrict__ knn,
        const float* __restrict__ Vm, const float* __restrict__ w1in,
        const float4* __restrict__ U,
        const float* __restrict__ bnpg, const float* __restrict__ bnpb,
        const float* __restrict__ Wp2, const float* __restrict__ bp2,
        const float* __restrict__ g2, const float* __restrict__ b2,
        const float* __restrict__ Ww2, const float* __restrict__ bw2,
        float* __restrict__ agg, float* __restrict__ st)
{
    __shared__ float sW2[8][8];
    __shared__ float sA8[8], sC8[8], sB8[8];
    __shared__ float wsm[8][8][16];   // [warp][o][ns]
    __shared__ float4 sNb[8][16];
    __shared__ float sS[64], sQ[64];
    const int tid = threadIdx.x, lane = tid & 31, wl = tid >> 5;
    if (tid < 64) { sW2[tid >> 3][tid & 7] = Ww2[tid]; sS[tid] = 0.f; sQ[tid] = 0.f; }
    if (tid < 8) {
        float m = st[272 + tid] * INV_P;
        float var = fmaf(-m, m, st[280 + tid] * INV_P);
        float a = g2[tid] * rsqrtf(var + EPSF);
        sA8[tid] = a; sC8[tid] = fmaf(-m, a, b2[tid]);
        sB8[tid] = bw2[tid];
    }
    __syncthreads();
    const int c0 = lane, c1 = lane + 32;
    float A0,A1,A2,C0,C1,C2; bnp_params(st, bnpg, bnpb, A0,A1,A2,C0,C1,C2);
    float P00=__ldg(&Wp2[c0]), P10=__ldg(&Wp2[64+c0]), P20=__ldg(&Wp2[128+c0]), B0=__ldg(&bp2[c0]);
    float P01=__ldg(&Wp2[c1]), P11=__ldg(&Wp2[64+c1]), P21=__ldg(&Wp2[128+c1]), B1=__ldg(&bp2[c1]);
    const int pair = lane >> 1, ob = (lane & 1) << 2;
    const int oo = lane & 7;
    float s0=0,q0=0,s1=0,q1=0;
    const int warp = (blockIdx.x * blockDim.x + tid) >> 5;
    const int nw = (gridDim.x * blockDim.x) >> 5;
    for (int n = warp; n < NPTS; n += nw) {
        // phase 1: logits
        {
            const float4* wp = (const float4*)(w1in + (long)n*128 + pair*8);
            float4 lo = wp[0], hi = wp[1];
            float rv[8] = {lo.x, lo.y, lo.z, lo.w, hi.x, hi.y, hi.z, hi.w};
#pragma unroll
            for (int i = 0; i < 8; i++) rv[i] = fmaxf(fmaf(rv[i], sA8[i], sC8[i]), 0.f);
#pragma unroll
            for (int j = 0; j < 4; j++) {
                int o = ob + j;
                float lg = sB8[o];
#pragma unroll
                for (int i = 0; i < 8; i++) lg = fmaf(rv[i], sW2[i][o], lg);
                wsm[wl][o][pair] = lg;
            }
        }
        // stage neighbor data while logits settle
        stage_nb(sNb[wl], n, lane, knn, U, A0,A1,A2, C0,C1,C2);
        // phase 2: softmax over ns
        if (lane < 8) {
            float* row = wsm[wl][lane];
            float4 v0 = *(float4*)&row[0], v1 = *(float4*)&row[4];
            float4 v2 = *(float4*)&row[8], v3 = *(float4*)&row[12];
            float m = fmaxf(fmaxf(fmaxf(v0.x,v0.y),fmaxf(v0.z,v0.w)),
                     fmaxf(fmaxf(fmaxf(v1.x,v1.y),fmaxf(v1.z,v1.w)),
                     fmaxf(fmaxf(fmaxf(v2.x,v2.y),fmaxf(v2.z,v2.w)),
                           fmaxf(fmaxf(v3.x,v3.y),fmaxf(v3.z,v3.w)))));
            v0.x=__expf(v0.x-m); v0.y=__expf(v0.y-m); v0.z=__expf(v0.z-m); v0.w=__expf(v0.w-m);
            v1.x=__expf(v1.x-m); v1.y=__expf(v1.y-m); v1.z=__expf(v1.z-m); v1.w=__expf(v1.w-m);
            v2.x=__expf(v2.x-m); v2.y=__expf(v2.y-m); v2.z=__expf(v2.z-m); v2.w=__expf(v2.w-m);
            v3.x=__expf(v3.x-m); v3.y=__expf(v3.y-m); v3.z=__expf(v3.z-m); v3.w=__expf(v3.w-m);
            float ssum = (v0.x+v0.y+v0.z+v0.w)+(v1.x+v1.y+v1.z+v1.w)
                        +(v2.x+v2.y+v2.z+v2.w)+(v3.x+v3.y+v3.z+v3.w);
            float inv = 1.f / ssum;
            v0.x*=inv; v0.y*=inv; v0.z*=inv; v0.w*=inv;
            v1.x*=inv; v1.y*=inv; v1.z*=inv; v1.w*=inv;
            v2.x*=inv; v2.y*=inv; v2.z*=inv; v2.w*=inv;
            v3.x*=inv; v3.y*=inv; v3.z*=inv; v3.w*=inv;
            *(float4*)&row[0]=v0; *(float4*)&row[4]=v1;
            *(float4*)&row[8]=v2; *(float4*)&row[12]=v3;
        }
        __syncwarp();
        // phase 3: batched gather + weighted aggregation
        float acc0 = 0.f, acc1 = 0.f;
        const float* wrow = wsm[wl][oo];
#pragma unroll
        for (int nb = 0; nb < 4; nb++) {
            float4 d0 = sNb[wl][nb*4+0];
            float4 d1 = sNb[wl][nb*4+1];
            float4 d2 = sNb[wl][nb*4+2];
            float4 d3 = sNb[wl][nb*4+3];
            float4 wt = *(const float4*)&wrow[nb*4];
            int v0o = __float_as_int(d0.x);
            int v1o = __float_as_int(d1.x);
            int v2o = __float_as_int(d2.x);
            int v3o = __float_as_int(d3.x);
            float va0 = Vm[v0o+c0], vb0 = Vm[v0o+c1];
            float va1 = Vm[v1o+c0], vb1 = Vm[v1o+c1];
            float va2 = Vm[v2o+c0], vb2 = Vm[v2o+c1];
            float va3 = Vm[v3o+c0], vb3 = Vm[v3o+c1];
            acc0 = fmaf(va0 + fmaf(d0.y,P00,fmaf(d0.z,P10,fmaf(d0.w,P20,B0))), wt.x, acc0);
            acc1 = fmaf(vb0 + fmaf(d0.y,P01,fmaf(d0.z,P11,fmaf(d0.w,P21,B1))), wt.x, acc1);
            acc0 = fmaf(va1 + fmaf(d1.y,P00,fmaf(d1.z,P10,fmaf(d1.w,P20,B0))), wt.y, acc0);
            acc1 = fmaf(vb1 + fmaf(d1.y,P01,fmaf(d1.z,P11,fmaf(d1.w,P21,B1))), wt.y, acc1);
            acc0 = fmaf(va2 + fmaf(d2.y,P00,fmaf(d2.z,P10,fmaf(d2.w,P20,B0))), wt.z, acc0);
            acc1 = fmaf(vb2 + fmaf(d2.y,P01,fmaf(d2.z,P11,fmaf(d2.w,P21,B1))), wt.z, acc1);
            acc0 = fmaf(va3 + fmaf(d3.y,P00,fmaf(d3.z,P10,fmaf(d3.w,P20,B0))), wt.w, acc0);
            acc1 = fmaf(vb3 + fmaf(d3.y,P01,fmaf(d3.z,P11,fmaf(d3.w,P21,B1))), wt.w, acc1);
        }
        agg[(long)n*64 + c0] = acc0;
        agg[(long)n*64 + c1] = acc1;
        s0 += acc0; q0 = fmaf(acc0,acc0,q0);
        s1 += acc1; q1 = fmaf(acc1,acc1,q1);
        __syncwarp();
    }
    atomicAdd(&sS[c0], s0); atomicAdd(&sQ[c0], q0);
    atomicAdd(&sS[c1], s1); atomicAdd(&sQ[c1], q1);
    __syncthreads();
    if (tid < 64) {
        atomicAdd(&st[288 + tid], sS[tid]);
        atomicAdd(&st[352 + tid], sQ[tid]);
    }
}

// ---------------------------------------------------------------------------
// gemm3: t3 = relu(bn2(agg)) @ W3, fused bn3 stats
__global__ void __launch_bounds__(256) k_gemm3(
        const float* __restrict__ X, const float* __restrict__ W,
        const float* __restrict__ st, const float* __restrict__ bg,
        const float* __restrict__ bb, float* __restrict__ out, float* __restrict__ sto)
{
    __shared__ float sX[64][65];
    __shared__ float sW[64][64];
    __shared__ float sA[64], sC[64];
    __shared__ float sS[64], sQ[64];
    const int tid = threadIdx.x;
    const long row0 = (long)blockIdx.x * 64;
    if (tid < 64) {
        sS[tid] = 0.f; sQ[tid] = 0.f;
        float m = st[288 + tid] * INV_N;
        float var = fmaf(-m, m, st[352 + tid] * INV_N);
        float a = bg[tid] * rsqrtf(var + EPSF);
        sA[tid] = a; sC[tid] = fmaf(-m, a, bb[tid]);
    }
    for (int i = tid; i < 4096; i += 256) sW[i >> 6][i & 63] = W[i];
    __syncthreads();
    for (int i = tid; i < 4096; i += 256) {
        int r = i >> 6, kk = i & 63;
        sX[r][kk] = fmaxf(fmaf(X[(row0 + r) * 64 + kk], sA[kk], sC[kk]), 0.f);
    }
    __syncthreads();
    const int lane = tid & 31;
    const int r = tid & 63, c0 = (tid >> 6) << 4;
    float acc[16];
#pragma unroll
    for (int j = 0; j < 16; j++) acc[j] = 0.f;
#pragma unroll
    for (int kk = 0; kk < 64; kk++) {
        float xv = sX[r][kk];
#pragma unroll
        for (int j = 0; j < 16; j++) acc[j] = fmaf(xv, sW[kk][c0 + j], acc[j]);
    }
    float* op = out + (row0 + r) * 64 + c0;
#pragma unroll
    for (int j = 0; j < 16; j++) op[j] = acc[j];
#pragma unroll
    for (int j = 0; j < 16; j++) {
        float s = acc[j], q = acc[j] * acc[j];
#pragma unroll
        for (int off = 16; off; off >>= 1) {
            s += __shfl_xor_sync(0xffffffffu, s, off);
            q += __shfl_xor_sync(0xffffffffu, q, off);
        }
        if (lane == 0) { atomicAdd(&sS[c0 + j], s); atomicAdd(&sQ[c0 + j], q); }
    }
    __syncthreads();
    if (tid < 64) {
        atomicAdd(&sto[416 + tid], sS[tid]);
        atomicAdd(&sto[480 + tid], sQ[tid]);
    }
}

// out = relu(bn3(t3) + x), bn3 params inline
__global__ void k_final(const float* __restrict__ T3, const float* __restrict__ X,
                        const float* __restrict__ st,
                        const float* __restrict__ g3, const float* __restrict__ b3,
                        float* __restrict__ out)
{
    __shared__ float sA[64], sC[64];
    const int tid = threadIdx.x;
    if (tid < 64) {
        float m = st[416 + tid] * INV_N;
        float var = fmaf(-m, m, st[480 + tid] * INV_N);
        float a = g3[tid] * rsqrtf(var + EPSF);
        sA[tid] = a; sC[tid] = fmaf(-m, a, b3[tid]);
    }
    __syncthreads();
    const int stride = gridDim.x * blockDim.x;
    for (int i = blockIdx.x * blockDim.x + tid; i < NPTS * 16; i += stride) {
        int cb = (i * 4) & 63;
        float4 t = ((const float4*)T3)[i];
        float4 x4 = ((const float4*)X)[i];
        float4 r;
        r.x = fmaxf(fmaf(t.x, sA[cb+0], sC[cb+0]) + x4.x, 0.f);
        r.y = fmaxf(fmaf(t.y, sA[cb+1], sC[cb+1]) + x4.y, 0.f);
        r.z = fmaxf(fmaf(t.z, sA[cb+2], sC[cb+2]) + x4.z, 0.f);
        r.w = fmaxf(fmaf(t.w, sA[cb+3], sC[cb+3]) + x4.w, 0.f);
        ((float4*)out)[i] = r;
    }
}

// ---------------------------------------------------------------------------
extern "C" void kernel_launch(void* const* d_in, const int* in_sizes, int n_in,
                              void* d_out, int out_size)
{
    const float* p     = (const float*)d_in[0];
    const float* x     = (const float*)d_in[1];
    const int*   knn   = (const int*)  d_in[2];
    const float* W1    = (const float*)d_in[3];
    const float* bn1g  = (const float*)d_in[4];
    const float* bn1b  = (const float*)d_in[5];
    const float* Wq    = (const float*)d_in[6];
    const float* bq    = (const float*)d_in[7];
    const float* Wk    = (const float*)d_in[8];
    const float* bk    = (const float*)d_in[9];
    const float* Wv    = (const float*)d_in[10];
    const float* bv    = (const float*)d_in[11];
    const float* Wp1   = (const float*)d_in[12];
    const float* bp1   = (const float*)d_in[13];
    const float* bnpg  = (const float*)d_in[14];
    const float* bnpb  = (const float*)d_in[15];
    const float* Wp2   = (const float*)d_in[16];
    const float* bp2   = (const float*)d_in[17];
    const float* bnw1g = (const float*)d_in[18];
    const float* bnw1b = (const float*)d_in[19];
    const float* Ww1   = (const float*)d_in[20];
    const float* bw1   = (const float*)d_in[21];
    const float* bnw2g = (const float*)d_in[22];
    const float* bnw2b = (const float*)d_in[23];
    const float* Ww2   = (const float*)d_in[24];
    const float* bw2   = (const float*)d_in[25];
    const float* bn2g  = (const float*)d_in[26];
    const float* bn2b  = (const float*)d_in[27];
    const float* W3    = (const float*)d_in[28];
    const float* bn3g  = (const float*)d_in[29];
    const float* bn3b  = (const float*)d_in[30];
    float* out = (float*)d_out;

    float* scr = nullptr;
    cudaGetSymbolAddress((void**)&scr, g_scr);
    float* t1  = scr + OFF_T1;
    float* qb  = scr + OFF_Q;
    float* kb  = scr + OFF_K;
    float* vb  = scr + OFF_V;
    float* w1b = scr + OFF_W1B;
    float* agg = scr + OFF_AGG;
    float* t3  = scr + OFF_T3;
    float4* U  = (float4*)(scr + OFF_U);
    float* st  = scr + OFF_STATS;

    k_zero<<<1, 544>>>(st);

    // gemm1 + pstats (heterogeneous grid, overlapped)
    k_g1p<<<GEMM_BLOCKS + PST_BLOCKS, 256>>>(x, W1, t1, st, p, knn, Wp1, bp1, U);

    // q,k,v (bn1 inline, fused 3-GEMM loop)
    k_qkv<<<GEMM_BLOCKS, 256>>>(t1, Wq, bq, Wk, bk, Wv, bv, st, bn1g, bn1b, qb, kb, vb);

    // bnw1 stats (verified best: launch_bounds(256,6), exact wave 148x6)
    k_wstats<<<888, 256>>>(knn, qb, kb, U, bnpg, bnpb, Wp2, bp2, st);

    // pass B (+ bnw2 stats) — R4-measured config
    k_passB<<<888, 256>>>(knn, qb, kb, U, bnpg, bnpb, Wp2, bp2,
                          bnw1g, bnw1b, Ww1, bw1, w1b, st);

    // pass C (+ bn2 stats) — R4-measured config
    k_passC<<<1184, 256>>>(knn, vb, w1b, U, bnpg, bnpb, Wp2, bp2,
                           bnw2g, bnw2b, Ww2, bw2, agg, st);

    // gemm3 (bn2 inline, + bn3 stats)
    k_gemm3<<<1250, 256>>>(agg, W3, st, bn2g, bn2b, t3, st);

    // residual + relu (bn3 inline)
    k_final<<<640, 256>>>(t3, x, st, bn3g, bn3b, out);
}